// round 13
// baseline (speedup 1.0000x reference)
#include <cuda_runtime.h>
#include <cuda_fp16.h>
#include <math.h>

#define Bsz 128
#define Ssz 256
#define Hsz 384
#define NHs 12
#define DHs 32
#define Fsz 1536
#define Lyr 6
#define NOFF 5
#define ROWS (Bsz*Ssz)   /* 32768 */

// ---------------- scratch (static device globals; no allocation) --------------
__device__ float  g_h[ROWS*Hsz];
__device__ __half g_hh[ROWS*Hsz];        // half copy of h (GEMM A input)
__device__ __half g_qh[ROWS*Hsz];
__device__ __half g_kh[ROWS*Hsz];
__device__ __half g_vh[ROWS*Hsz];
__device__ __half g_ctxh[ROWS*Hsz];      // attention output (half, feeds O-proj)
__device__ __half g_tmph[ROWS*Hsz];      // residual delta (half)
__device__ __half g_ffh[ROWS*Fsz];       // FFN intermediate (half)
__device__ float  g_pooled[Bsz*Hsz];
__device__ int    g_active[Bsz];
__device__ float  g_scores[Bsz];
__device__ int    g_exitl[Bsz];
// transposed half weights: Wt[n][k] = (half)W[k][n]
__device__ __half g_whq[Lyr*Hsz*Hsz];
__device__ __half g_whk[Lyr*Hsz*Hsz];
__device__ __half g_whv[Lyr*Hsz*Hsz];
__device__ __half g_who[Lyr*Hsz*Hsz];
__device__ __half g_whi[Lyr*Hsz*Fsz];
__device__ __half g_whfo[Lyr*Fsz*Hsz];

// ---------------- helpers ------------------------------------------------------
__device__ __forceinline__ float blockReduceSum128(float val, float* smem4) {
    int lane = threadIdx.x & 31, warp = threadIdx.x >> 5;
    #pragma unroll
    for (int o = 16; o > 0; o >>= 1) val += __shfl_down_sync(0xffffffffu, val, o);
    if (lane == 0) smem4[warp] = val;
    __syncthreads();
    float v = (threadIdx.x < 4) ? smem4[threadIdx.x] : 0.f;
    if (warp == 0) {
        v += __shfl_down_sync(0xffffffffu, v, 2);
        v += __shfl_down_sync(0xffffffffu, v, 1);
        if (lane == 0) smem4[0] = v;
    }
    __syncthreads();
    float r = smem4[0];
    __syncthreads();
    return r;
}

__device__ __forceinline__ void cpasync16(void* dst, const void* src) {
    unsigned sa = (unsigned)__cvta_generic_to_shared(dst);
    asm volatile("cp.async.cg.shared.global [%0], [%1], 16;\n" :: "r"(sa), "l"(src));
}
__device__ __forceinline__ void cp_commit() { asm volatile("cp.async.commit_group;\n"); }
__device__ __forceinline__ void cp_wait0()  { asm volatile("cp.async.wait_group 0;\n"); }

#define MMA_F16(d, a, bfr) \
    asm volatile("mma.sync.aligned.m16n8k16.row.col.f32.f16.f16.f32 " \
        "{%0,%1,%2,%3}, {%4,%5,%6,%7}, {%8,%9}, {%0,%1,%2,%3};" \
        : "+f"((d)[0]), "+f"((d)[1]), "+f"((d)[2]), "+f"((d)[3]) \
        : "r"((a)[0]), "r"((a)[1]), "r"((a)[2]), "r"((a)[3]), \
          "r"((bfr)[0]), "r"((bfr)[1]))

// ---------------- state init ---------------------------------------------------
__global__ void init_state_kernel() {
    int t = threadIdx.x;
    if (t < Bsz) { g_active[t] = 1; g_scores[t] = 0.f; g_exitl[t] = 0; }
}

// ---------------- weight transpose + fp16 convert: dst[n][k] = (half)src[k][n] -
__global__ void transpose_h_kernel(const float* __restrict__ src, __half* __restrict__ dst,
                                   int K, int N) {
    __shared__ float tile[32][33];
    const float* s = src + (size_t)blockIdx.z * K * N;
    __half* d = dst + (size_t)blockIdx.z * K * N;
    int n0 = blockIdx.x * 32, k0 = blockIdx.y * 32;
    #pragma unroll
    for (int i = threadIdx.y; i < 32; i += 8)
        tile[i][threadIdx.x] = s[(size_t)(k0 + i) * N + n0 + threadIdx.x];
    __syncthreads();
    #pragma unroll
    for (int i = threadIdx.y; i < 32; i += 8)
        d[(size_t)(n0 + i) * K + k0 + threadIdx.x] = __float2half_rn(tile[threadIdx.x][i]);
}

// ---------------- embeddings + LN (writes fp32 h and half copy) ----------------
__global__ void embed_ln_kernel(const int* __restrict__ ids, const int* __restrict__ tts,
                                const float* __restrict__ we, const float* __restrict__ pe,
                                const float* __restrict__ te, const float* __restrict__ g,
                                const float* __restrict__ b) {
    __shared__ float red[4];
    int row = blockIdx.x, s = row & (Ssz - 1), tid = threadIdx.x;
    int id = ids[row], tt = tts[row];
    float x[3];
    #pragma unroll
    for (int i = 0; i < 3; i++) {
        int j = tid + i * 128;
        x[i] = we[id * Hsz + j] + pe[s * Hsz + j] + te[tt * Hsz + j];
    }
    float mean = blockReduceSum128(x[0] + x[1] + x[2], red) * (1.f / Hsz);
    float sq = 0.f;
    #pragma unroll
    for (int i = 0; i < 3; i++) { float d = x[i] - mean; sq += d * d; }
    float var = blockReduceSum128(sq, red) * (1.f / Hsz);
    float inv = rsqrtf(var + 1e-12f);
    #pragma unroll
    for (int i = 0; i < 3; i++) {
        int j = tid + i * 128;
        float o = g[j] * (x[i] - mean) * inv + b[j];
        g_h[(size_t)row * Hsz + j] = o;
        g_hh[(size_t)row * Hsz + j] = __float2half_rn(o);
    }
}

// ---------------- FP16 tensor-core GEMM (128x128 block, 64x64 warp tile) -------
struct HgemmSmem {
    __half As[2][128][40];
    __half Bs[2][128][40];
};

__device__ __forceinline__ void hgemm_body(
        const __half* __restrict__ A, const __half* __restrict__ Wt,
        const float* __restrict__ bias, float* __restrict__ Cf, __half* __restrict__ Ch,
        int N, int K, int act, int bx, int by, HgemmSmem& sm) {
    const int t = threadIdx.x;     // 128
    const int lane = t & 31, warp = t >> 5;
    const int kk = lane & 3, gr = lane >> 2;
    const int mw = (warp >> 1) * 64;
    const int nw = (warp & 1) * 64;
    const int br = by * 128, bc = bx * 128;

    const int rbase = t >> 2, cc = t & 3;
    const __half* Ag = A + (size_t)(br + rbase) * K + cc * 8;
    const __half* Bg = Wt + (size_t)(bc + rbase) * K + cc * 8;

    float acc[4][8][4] = {};
    const int T = K >> 5;

    #define HGL(k0, buf) do { \
        _Pragma("unroll") \
        for (int i_ = 0; i_ < 4; i_++) { \
            cpasync16(&sm.As[buf][rbase + 32*i_][cc*8], Ag + (size_t)(32*i_) * K + (k0)); \
            cpasync16(&sm.Bs[buf][rbase + 32*i_][cc*8], Bg + (size_t)(32*i_) * K + (k0)); \
        } \
        cp_commit(); \
    } while (0)

    HGL(0, 0);
    int buf = 0;
    for (int tt = 0; tt < T; tt++) {
        cp_wait0();
        __syncthreads();
        if (tt + 1 < T) HGL((tt + 1) << 5, buf ^ 1);
        #pragma unroll
        for (int ks = 0; ks < 32; ks += 16) {
            unsigned a[4][4], b[8][2];
            #pragma unroll
            for (int mt = 0; mt < 4; mt++) {
                int m = mw + mt * 16 + gr;
                a[mt][0] = *(const unsigned*)&sm.As[buf][m][ks + 2*kk];
                a[mt][1] = *(const unsigned*)&sm.As[buf][m + 8][ks + 2*kk];
                a[mt][2] = *(const unsigned*)&sm.As[buf][m][ks + 2*kk + 8];
                a[mt][3] = *(const unsigned*)&sm.As[buf][m + 8][ks + 2*kk + 8];
            }
            #pragma unroll
            for (int nt = 0; nt < 8; nt++) {
                int n = nw + nt * 8 + gr;
                b[nt][0] = *(const unsigned*)&sm.Bs[buf][n][ks + 2*kk];
                b[nt][1] = *(const unsigned*)&sm.Bs[buf][n][ks + 2*kk + 8];
            }
            #pragma unroll
            for (int mt = 0; mt < 4; mt++)
                #pragma unroll
                for (int nt = 0; nt < 8; nt++)
                    MMA_F16(acc[mt][nt], a[mt], b[nt]);
        }
        __syncthreads();
        buf ^= 1;
    }
    #undef HGL

    #pragma unroll
    for (int nt = 0; nt < 8; nt++) {
        int col = bc + nw + nt * 8 + 2 * kk;
        float b0 = bias[col], b1 = bias[col + 1];
        #pragma unroll
        for (int mt = 0; mt < 4; mt++) {
            int row = br + mw + mt * 16 + gr;
            float v0 = acc[mt][nt][0] + b0, v1 = acc[mt][nt][1] + b1;
            float v2 = acc[mt][nt][2] + b0, v3 = acc[mt][nt][3] + b1;
            if (act == 1) {
                v0 = 0.5f * v0 * (1.f + erff(v0 * 0.70710678118654752f));
                v1 = 0.5f * v1 * (1.f + erff(v1 * 0.70710678118654752f));
                v2 = 0.5f * v2 * (1.f + erff(v2 * 0.70710678118654752f));
                v3 = 0.5f * v3 * (1.f + erff(v3 * 0.70710678118654752f));
            }
            if (Ch) {
                *reinterpret_cast<__half2*>(&Ch[(size_t)row * N + col]) =
                    __floats2half2_rn(v0, v1);
                *reinterpret_cast<__half2*>(&Ch[(size_t)(row + 8) * N + col]) =
                    __floats2half2_rn(v2, v3);
            } else {
                *reinterpret_cast<float2*>(&Cf[(size_t)row * N + col]) = make_float2(v0, v1);
                *reinterpret_cast<float2*>(&Cf[(size_t)(row + 8) * N + col]) = make_float2(v2, v3);
            }
        }
    }
}

__global__ __launch_bounds__(128, 2) void hgemm_kernel(
        const __half* __restrict__ A, const __half* __restrict__ Wt,
        const float* __restrict__ bias, float* __restrict__ Cf, __half* __restrict__ Ch,
        int N, int K, int act) {
    __shared__ HgemmSmem sm;
    hgemm_body(A, Wt, bias, Cf, Ch, N, K, act, blockIdx.x, blockIdx.y, sm);
}

__global__ __launch_bounds__(128, 2) void hgemm_qkv_kernel(
        const __half* __restrict__ A,
        const __half* __restrict__ Wtq, const __half* __restrict__ Wtk, const __half* __restrict__ Wtv,
        const float* __restrict__ bq, const float* __restrict__ bk, const float* __restrict__ bv,
        __half* __restrict__ Cq, __half* __restrict__ Ck, __half* __restrict__ Cv) {
    __shared__ HgemmSmem sm;
    const __half* Ws[3] = {Wtq, Wtk, Wtv};
    const float* bs[3] = {bq, bk, bv};
    __half* Cs[3] = {Cq, Ck, Cv};
    int z = blockIdx.z;
    hgemm_body(A, Ws[z], bs[z], (float*)0, Cs[z], Hsz, Hsz, 0, blockIdx.x, blockIdx.y, sm);
}

// ---------------- fp16 tensor-core flash attention -----------------------------
#define ATTN_SMEM_BYTES (256*40*2 + 32*264*2 + 8*32*40*2 + 256*4)
#define SCL 0.17677669529663688f

__global__ __launch_bounds__(256, 3) void attn_mma_kernel(
        const __half* __restrict__ q, const __half* __restrict__ k,
        const __half* __restrict__ v, const int* __restrict__ mask,
        __half* __restrict__ ctx) {
    extern __shared__ char smraw[];
    __half* Ksh = reinterpret_cast<__half*>(smraw);              // [256][40]
    __half* Vth = Ksh + 256*40;                                  // [32][264]
    __half* Pwh = Vth + 32*264;                                  // [8][32][40]
    float*  bi  = reinterpret_cast<float*>(Pwh + 8*32*40);       // [256]

    const int h = blockIdx.x, b = blockIdx.y;
    const int tid = threadIdx.x, lane = tid & 31, w = tid >> 5;
    const int gr = lane >> 2, kk = lane & 3;

    for (int idx = tid; idx < 256*32; idx += 256) {
        int key = idx >> 5, d = idx & 31;
        size_t gi = (size_t)(b*Ssz + key)*Hsz + h*DHs + d;
        Ksh[key*40 + d] = k[gi];
        Vth[d*264 + key] = v[gi];
    }
    bi[tid] = (1.f - (float)mask[b*Ssz + tid]) * -1e9f;
    __syncthreads();

    unsigned aq[2][2][4];
    const int qrow0 = b*Ssz + w*32 + gr;
    #pragma unroll
    for (int mt = 0; mt < 2; mt++)
        #pragma unroll
        for (int kt = 0; kt < 2; kt++) {
            const __half* qp = q + (size_t)(qrow0 + mt*16)*Hsz + h*DHs + kt*16 + 2*kk;
            aq[mt][kt][0] = *(const unsigned*)qp;
            aq[mt][kt][1] = *(const unsigned*)(qp + 8*(size_t)Hsz);
            aq[mt][kt][2] = *(const unsigned*)(qp + 8);
            aq[mt][kt][3] = *(const unsigned*)(qp + 8*(size_t)Hsz + 8);
        }

    float m_[2][2] = {{-1e30f, -1e30f}, {-1e30f, -1e30f}};
    float l_[2][2] = {};
    float o[2][4][4] = {};
    __half* pw = Pwh + w*(32*40);

    for (int t = 0; t < 8; t++) {
        const int kb = t*32;
        float s[2][4][4] = {};
        #pragma unroll
        for (int kt = 0; kt < 2; kt++) {
            unsigned bf[4][2];
            #pragma unroll
            for (int nt = 0; nt < 4; nt++) {
                const __half* kp = &Ksh[(kb + nt*8 + gr)*40 + kt*16 + 2*kk];
                bf[nt][0] = *(const unsigned*)kp;
                bf[nt][1] = *(const unsigned*)(kp + 8);
            }
            #pragma unroll
            for (int mt = 0; mt < 2; mt++)
                #pragma unroll
                for (int nt = 0; nt < 4; nt++)
                    MMA_F16(s[mt][nt], aq[mt][kt], bf[nt]);
        }
        #pragma unroll
        for (int nt = 0; nt < 4; nt++) {
            float2 bv = *reinterpret_cast<const float2*>(&bi[kb + nt*8 + 2*kk]);
            #pragma unroll
            for (int mt = 0; mt < 2; mt++) {
                s[mt][nt][0] = s[mt][nt][0]*SCL + bv.x;
                s[mt][nt][1] = s[mt][nt][1]*SCL + bv.y;
                s[mt][nt][2] = s[mt][nt][2]*SCL + bv.x;
                s[mt][nt][3] = s[mt][nt][3]*SCL + bv.y;
            }
        }
        #pragma unroll
        for (int mt = 0; mt < 2; mt++) {
            #pragma unroll
            for (int hf = 0; hf < 2; hf++) {
                float tm = -1e30f;
                #pragma unroll
                for (int nt = 0; nt < 4; nt++)
                    tm = fmaxf(tm, fmaxf(s[mt][nt][2*hf], s[mt][nt][2*hf+1]));
                tm = fmaxf(tm, __shfl_xor_sync(0xffffffffu, tm, 1));
                tm = fmaxf(tm, __shfl_xor_sync(0xffffffffu, tm, 2));
                float nm = fmaxf(m_[mt][hf], tm);
                float corr = __expf(m_[mt][hf] - nm);
                m_[mt][hf] = nm;
                float rs = 0.f;
                #pragma unroll
                for (int nt = 0; nt < 4; nt++) {
                    float p0 = __expf(s[mt][nt][2*hf] - nm);
                    float p1 = __expf(s[mt][nt][2*hf+1] - nm);
                    s[mt][nt][2*hf] = p0; s[mt][nt][2*hf+1] = p1;
                    rs += p0 + p1;
                    o[mt][nt][2*hf]   *= corr;
                    o[mt][nt][2*hf+1] *= corr;
                }
                rs += __shfl_xor_sync(0xffffffffu, rs, 1);
                rs += __shfl_xor_sync(0xffffffffu, rs, 2);
                l_[mt][hf] = l_[mt][hf]*corr + rs;
            }
        }
        #pragma unroll
        for (int mt = 0; mt < 2; mt++)
            #pragma unroll
            for (int nt = 0; nt < 4; nt++) {
                *reinterpret_cast<__half2*>(&pw[(mt*16+gr)*40 + nt*8 + 2*kk]) =
                    __floats2half2_rn(s[mt][nt][0], s[mt][nt][1]);
                *reinterpret_cast<__half2*>(&pw[(mt*16+gr+8)*40 + nt*8 + 2*kk]) =
                    __floats2half2_rn(s[mt][nt][2], s[mt][nt][3]);
            }
        __syncwarp();
        #pragma unroll
        for (int kt = 0; kt < 2; kt++) {
            unsigned ap[2][4];
            #pragma unroll
            for (int mt = 0; mt < 2; mt++) {
                const __half* pp = &pw[(mt*16+gr)*40 + kt*16 + 2*kk];
                ap[mt][0] = *(const unsigned*)pp;
                ap[mt][1] = *(const unsigned*)(pp + 8*40);
                ap[mt][2] = *(const unsigned*)(pp + 8);
                ap[mt][3] = *(const unsigned*)(pp + 8*40 + 8);
            }
            unsigned bf[4][2];
            #pragma unroll
            for (int nt = 0; nt < 4; nt++) {
                const __half* vp = &Vth[(nt*8+gr)*264 + kb + kt*16 + 2*kk];
                bf[nt][0] = *(const unsigned*)vp;
                bf[nt][1] = *(const unsigned*)(vp + 8);
            }
            #pragma unroll
            for (int mt = 0; mt < 2; mt++)
                #pragma unroll
                for (int nt = 0; nt < 4; nt++)
                    MMA_F16(o[mt][nt], ap[mt], bf[nt]);
        }
        __syncwarp();
    }

    #pragma unroll
    for (int mt = 0; mt < 2; mt++) {
        float i0 = 1.f / l_[mt][0], i1 = 1.f / l_[mt][1];
        #pragma unroll
        for (int nt = 0; nt < 4; nt++) {
            size_t base = (size_t)(qrow0 + mt*16)*Hsz + h*DHs + nt*8 + 2*kk;
            *reinterpret_cast<__half2*>(&ctx[base]) =
                __floats2half2_rn(o[mt][nt][0]*i0, o[mt][nt][1]*i0);
            *reinterpret_cast<__half2*>(&ctx[base + 8*(size_t)Hsz]) =
                __floats2half2_rn(o[mt][nt][2]*i1, o[mt][nt][3]*i1);
        }
    }
}

// ---------------- residual + LN (warp per row; half delta; writes f32 + half) --
__global__ __launch_bounds__(256) void residual_ln_kernel(
        const __half* __restrict__ delta,
        const float* __restrict__ g, const float* __restrict__ b) {
    const int lane = threadIdx.x & 31, w = threadIdx.x >> 5;
    const int row = blockIdx.x * 8 + w;
    const float4* hp = reinterpret_cast<const float4*>(g_h + (size_t)row * Hsz);
    const __half2* dp = reinterpret_cast<const __half2*>(delta + (size_t)row * Hsz);
    float4 x[3];
    float sum = 0.f;
    #pragma unroll
    for (int i = 0; i < 3; i++) {
        int j = lane + i * 32;
        float4 hv = hp[j];
        float2 d0 = __half22float2(dp[2*j]);
        float2 d1 = __half22float2(dp[2*j + 1]);
        x[i] = make_float4(hv.x + d0.x, hv.y + d0.y, hv.z + d1.x, hv.w + d1.y);
        sum += x[i].x + x[i].y + x[i].z + x[i].w;
    }
    #pragma unroll
    for (int o = 16; o > 0; o >>= 1) sum += __shfl_xor_sync(0xffffffffu, sum, o);
    float mean = sum * (1.f / Hsz);
    float sq = 0.f;
    #pragma unroll
    for (int i = 0; i < 3; i++) {
        float dx = x[i].x - mean, dy = x[i].y - mean, dz = x[i].z - mean, dw = x[i].w - mean;
        sq += dx*dx + dy*dy + dz*dz + dw*dw;
    }
    #pragma unroll
    for (int o = 16; o > 0; o >>= 1) sq += __shfl_xor_sync(0xffffffffu, sq, o);
    float inv = rsqrtf(sq * (1.f / Hsz) + 1e-12f);
    float4* op = reinterpret_cast<float4*>(g_h + (size_t)row * Hsz);
    __half2* oph = reinterpret_cast<__half2*>(g_hh + (size_t)row * Hsz);
    const float4* gp = reinterpret_cast<const float4*>(g);
    const float4* bp = reinterpret_cast<const float4*>(b);
    #pragma unroll
    for (int i = 0; i < 3; i++) {
        int j = lane + i * 32;
        float4 gv = gp[j], bv = bp[j];
        float4 r = make_float4(gv.x * (x[i].x - mean) * inv + bv.x,
                               gv.y * (x[i].y - mean) * inv + bv.y,
                               gv.z * (x[i].z - mean) * inv + bv.z,
                               gv.w * (x[i].w - mean) * inv + bv.w);
        op[j] = r;
        oph[2*j]     = __floats2half2_rn(r.x, r.y);
        oph[2*j + 1] = __floats2half2_rn(r.z, r.w);
    }
}

// ---------------- offramp ------------------------------------------------------
__global__ void offramp_kernel(const float* __restrict__ Wr, const float* __restrict__ br,
                               int layer) {
    __shared__ float w[Hsz];
    int tid = threadIdx.x;  // 128
    #pragma unroll
    for (int i = 0; i < 3; i++) w[tid + i * 128] = Wr[layer * Hsz + tid + i * 128];
    __syncthreads();
    int b = tid;
    const float* hr = g_h + (size_t)(b * Ssz) * Hsz;
    float l = br[layer];
    for (int kk = 0; kk < Hsz; kk++) l = fmaf(hr[kk], w[kk], l);
    float lsp = (l > 0.f) ? -log1pf(expf(-l)) : (l - log1pf(expf(l)));
    float lsn = (l < 0.f) ? -log1pf(expf(l)) : (-l - log1pf(expf(-l)));
    float p = 1.f / (1.f + expf(-l));
    float ent = -(p * lsp + (1.f - p) * lsn);
    if (g_active[b] && ent < 0.1f) {
        g_scores[b] = l; g_exitl[b] = layer; g_active[b] = 0;
    }
}

// ---------------- pooler -------------------------------------------------------
__global__ void pooler_kernel(const float* __restrict__ Wp, const float* __restrict__ bp) {
    __shared__ float hr[Hsz];
    int b = blockIdx.x, tid = threadIdx.x;   // 384 threads
    hr[tid] = g_h[(size_t)(b * Ssz) * Hsz + tid];
    __syncthreads();
    float acc = bp[tid];
    for (int kk = 0; kk < Hsz; kk++) acc = fmaf(hr[kk], Wp[kk * Hsz + tid], acc);
    g_pooled[b * Hsz + tid] = tanhf(acc);
}

// ---------------- final classifier + output ------------------------------------
__global__ void final_kernel(const float* __restrict__ Wc, const float* __restrict__ bc,
                             float* __restrict__ out, int out_size) {
    __shared__ int counts[8];
    int tid = threadIdx.x;  // 128
    if (tid < 8) counts[tid] = 0;
    __syncthreads();
    int b = tid;
    float acc = bc[0];
    for (int kk = 0; kk < Hsz; kk++) acc = fmaf(g_pooled[b * Hsz + kk], Wc[kk], acc);
    float sc; int el;
    if (g_active[b]) { sc = acc; el = NOFF; }
    else             { sc = g_scores[b]; el = g_exitl[b]; }
    atomicAdd(&counts[el], 1);
    __syncthreads();
    out[b] = sc;
    out[Bsz + b] = (float)el;
    if (tid < NOFF + 1) out[2 * Bsz + tid] = (float)counts[tid];
    for (int i = 2 * Bsz + NOFF + 1 + tid; i < out_size; i += 128) out[i] = 0.f;
}

// ---------------- launch -------------------------------------------------------
extern "C" void kernel_launch(void* const* d_in, const int* in_sizes, int n_in,
                              void* d_out, int out_size) {
    (void)in_sizes; (void)n_in;
    const int*   input_ids      = (const int*)d_in[0];
    const int*   attention_mask = (const int*)d_in[1];
    const int*   token_type_ids = (const int*)d_in[2];
    const float* word_emb = (const float*)d_in[3];
    const float* pos_emb  = (const float*)d_in[4];
    const float* type_emb = (const float*)d_in[5];
    const float* emb_ln_g = (const float*)d_in[6];
    const float* emb_ln_b = (const float*)d_in[7];
    const float* Wq = (const float*)d_in[8];  const float* bq = (const float*)d_in[9];
    const float* Wk = (const float*)d_in[10]; const float* bk = (const float*)d_in[11];
    const float* Wv = (const float*)d_in[12]; const float* bv = (const float*)d_in[13];
    const float* Wo = (const float*)d_in[14]; const float* bo = (const float*)d_in[15];
    const float* ln1_g = (const float*)d_in[16]; const float* ln1_b = (const float*)d_in[17];
    const float* Wi = (const float*)d_in[18]; const float* bi = (const float*)d_in[19];
    const float* Wfo = (const float*)d_in[20]; const float* bfo = (const float*)d_in[21];
    const float* ln2_g = (const float*)d_in[22]; const float* ln2_b = (const float*)d_in[23];
    const float* Wp = (const float*)d_in[24]; const float* bp = (const float*)d_in[25];
    const float* Wc = (const float*)d_in[26]; const float* bc = (const float*)d_in[27];
    const float* Wr = (const float*)d_in[28]; const float* br = (const float*)d_in[29];

    __half *hhp, *qh, *kh, *vh, *ctxh, *tmph, *ffh;
    __half *whq, *whk, *whv, *who, *whi, *whfo;
    cudaGetSymbolAddress((void**)&hhp, g_hh);
    cudaGetSymbolAddress((void**)&qh, g_qh);
    cudaGetSymbolAddress((void**)&kh, g_kh);
    cudaGetSymbolAddress((void**)&vh, g_vh);
    cudaGetSymbolAddress((void**)&ctxh, g_ctxh);
    cudaGetSymbolAddress((void**)&tmph, g_tmph);
    cudaGetSymbolAddress((void**)&ffh, g_ffh);
    cudaGetSymbolAddress((void**)&whq, g_whq);
    cudaGetSymbolAddress((void**)&whk, g_whk);
    cudaGetSymbolAddress((void**)&whv, g_whv);
    cudaGetSymbolAddress((void**)&who, g_who);
    cudaGetSymbolAddress((void**)&whi, g_whi);
    cudaGetSymbolAddress((void**)&whfo, g_whfo);

    cudaFuncSetAttribute(attn_mma_kernel,
                         cudaFuncAttributeMaxDynamicSharedMemorySize, ATTN_SMEM_BYTES);

    init_state_kernel<<<1, 128>>>();
    embed_ln_kernel<<<ROWS, 128>>>(input_ids, token_type_ids, word_emb, pos_emb, type_emb,
                                   emb_ln_g, emb_ln_b);

    dim3 tb(32, 8);
    transpose_h_kernel<<<dim3(Hsz/32, Hsz/32, Lyr), tb>>>(Wq,  whq,  Hsz, Hsz);
    transpose_h_kernel<<<dim3(Hsz/32, Hsz/32, Lyr), tb>>>(Wk,  whk,  Hsz, Hsz);
    transpose_h_kernel<<<dim3(Hsz/32, Hsz/32, Lyr), tb>>>(Wv,  whv,  Hsz, Hsz);
    transpose_h_kernel<<<dim3(Hsz/32, Hsz/32, Lyr), tb>>>(Wo,  who,  Hsz, Hsz);
    transpose_h_kernel<<<dim3(Fsz/32, Hsz/32, Lyr), tb>>>(Wi,  whi,  Hsz, Fsz);
    transpose_h_kernel<<<dim3(Hsz/32, Fsz/32, Lyr), tb>>>(Wfo, whfo, Fsz, Hsz);

    dim3 gHH(Hsz / 128, ROWS / 128);          // (3, 256)
    dim3 gQKV(Hsz / 128, ROWS / 128, 3);      // (3, 256, 3)
    dim3 gHF(Fsz / 128, ROWS / 128);          // (12, 256)

    for (int i = 0; i < Lyr; i++) {
        hgemm_qkv_kernel<<<gQKV, 128>>>(hhp,
                    whq + (size_t)i * Hsz * Hsz, whk + (size_t)i * Hsz * Hsz,
                    whv + (size_t)i * Hsz * Hsz,
                    bq + i * Hsz, bk + i * Hsz, bv + i * Hsz,
                    qh, kh, vh);
        attn_mma_kernel<<<dim3(NHs, Bsz), 256, ATTN_SMEM_BYTES>>>(qh, kh, vh,
                                                                  attention_mask, ctxh);
        hgemm_kernel<<<gHH, 128>>>(ctxh, who + (size_t)i * Hsz * Hsz,
                                   bo + i * Hsz, (float*)0, tmph, Hsz, Hsz, 0);
        residual_ln_kernel<<<ROWS / 8, 256>>>(tmph, ln1_g + i * Hsz, ln1_b + i * Hsz);
        hgemm_kernel<<<gHF, 128>>>(hhp, whi + (size_t)i * Hsz * Fsz,
                                   bi + i * Fsz, (float*)0, ffh, Fsz, Hsz, 1);
        hgemm_kernel<<<gHH, 128>>>(ffh, whfo + (size_t)i * Fsz * Hsz,
                                   bfo + i * Hsz, (float*)0, tmph, Hsz, Fsz, 0);
        residual_ln_kernel<<<ROWS / 8, 256>>>(tmph, ln2_g + i * Hsz, ln2_b + i * Hsz);
        if (i < NOFF) {
            offramp_kernel<<<1, 128>>>(Wr, br, i);
        }
    }
    pooler_kernel<<<Bsz, Hsz>>>(Wp, bp);
    final_kernel<<<1, 128>>>(Wc, bc, (float*)d_out, out_size);
}

// round 14
// speedup vs baseline: 1.0389x; 1.0389x over previous
#include <cuda_runtime.h>
#include <cuda_fp16.h>
#include <math.h>

#define Bsz 128
#define Ssz 256
#define Hsz 384
#define NHs 12
#define DHs 32
#define Fsz 1536
#define Lyr 6
#define NOFF 5
#define ROWS (Bsz*Ssz)   /* 32768 */

// ---------------- scratch (static device globals; no allocation) --------------
__device__ float  g_h[ROWS*Hsz];
__device__ __half g_hh[ROWS*Hsz];        // half copy of h (GEMM A input)
__device__ __half g_qh[ROWS*Hsz];
__device__ __half g_kh[ROWS*Hsz];
__device__ __half g_vh[ROWS*Hsz];
__device__ __half g_ctxh[ROWS*Hsz];      // attention output (half, feeds O-proj)
__device__ __half g_tmph[ROWS*Hsz];      // residual delta (half)
__device__ __half g_ffh[ROWS*Fsz];       // FFN intermediate (half)
__device__ float  g_pooled[Bsz*Hsz];
__device__ int    g_active[Bsz];
__device__ float  g_scores[Bsz];
__device__ int    g_exitl[Bsz];
// transposed half weights: Wt[n][k] = (half)W[k][n]
__device__ __half g_whq[Lyr*Hsz*Hsz];
__device__ __half g_whk[Lyr*Hsz*Hsz];
__device__ __half g_whv[Lyr*Hsz*Hsz];
__device__ __half g_who[Lyr*Hsz*Hsz];
__device__ __half g_whi[Lyr*Hsz*Fsz];
__device__ __half g_whfo[Lyr*Fsz*Hsz];

// ---------------- helpers ------------------------------------------------------
__device__ __forceinline__ float blockReduceSum128(float val, float* smem4) {
    int lane = threadIdx.x & 31, warp = threadIdx.x >> 5;
    #pragma unroll
    for (int o = 16; o > 0; o >>= 1) val += __shfl_down_sync(0xffffffffu, val, o);
    if (lane == 0) smem4[warp] = val;
    __syncthreads();
    float v = (threadIdx.x < 4) ? smem4[threadIdx.x] : 0.f;
    if (warp == 0) {
        v += __shfl_down_sync(0xffffffffu, v, 2);
        v += __shfl_down_sync(0xffffffffu, v, 1);
        if (lane == 0) smem4[0] = v;
    }
    __syncthreads();
    float r = smem4[0];
    __syncthreads();
    return r;
}

__device__ __forceinline__ void cpasync16(void* dst, const void* src) {
    unsigned sa = (unsigned)__cvta_generic_to_shared(dst);
    asm volatile("cp.async.cg.shared.global [%0], [%1], 16;\n" :: "r"(sa), "l"(src));
}
__device__ __forceinline__ void cp_commit() { asm volatile("cp.async.commit_group;\n"); }
__device__ __forceinline__ void cp_wait0()  { asm volatile("cp.async.wait_group 0;\n"); }

#define MMA_F16(d, a, bfr) \
    asm volatile("mma.sync.aligned.m16n8k16.row.col.f32.f16.f16.f32 " \
        "{%0,%1,%2,%3}, {%4,%5,%6,%7}, {%8,%9}, {%0,%1,%2,%3};" \
        : "+f"((d)[0]), "+f"((d)[1]), "+f"((d)[2]), "+f"((d)[3]) \
        : "r"((a)[0]), "r"((a)[1]), "r"((a)[2]), "r"((a)[3]), \
          "r"((bfr)[0]), "r"((bfr)[1]))

// ---------------- state init ---------------------------------------------------
__global__ void init_state_kernel() {
    int t = threadIdx.x;
    if (t < Bsz) { g_active[t] = 1; g_scores[t] = 0.f; g_exitl[t] = 0; }
}

// ---------------- weight transpose + fp16 convert: dst[n][k] = (half)src[k][n] -
__global__ void transpose_h_kernel(const float* __restrict__ src, __half* __restrict__ dst,
                                   int K, int N) {
    __shared__ float tile[32][33];
    const float* s = src + (size_t)blockIdx.z * K * N;
    __half* d = dst + (size_t)blockIdx.z * K * N;
    int n0 = blockIdx.x * 32, k0 = blockIdx.y * 32;
    #pragma unroll
    for (int i = threadIdx.y; i < 32; i += 8)
        tile[i][threadIdx.x] = s[(size_t)(k0 + i) * N + n0 + threadIdx.x];
    __syncthreads();
    #pragma unroll
    for (int i = threadIdx.y; i < 32; i += 8)
        d[(size_t)(n0 + i) * K + k0 + threadIdx.x] = __float2half_rn(tile[threadIdx.x][i]);
}

// ---------------- embeddings + LN (writes fp32 h and half copy) ----------------
__global__ void embed_ln_kernel(const int* __restrict__ ids, const int* __restrict__ tts,
                                const float* __restrict__ we, const float* __restrict__ pe,
                                const float* __restrict__ te, const float* __restrict__ g,
                                const float* __restrict__ b) {
    __shared__ float red[4];
    int row = blockIdx.x, s = row & (Ssz - 1), tid = threadIdx.x;
    int id = ids[row], tt = tts[row];
    float x[3];
    #pragma unroll
    for (int i = 0; i < 3; i++) {
        int j = tid + i * 128;
        x[i] = we[id * Hsz + j] + pe[s * Hsz + j] + te[tt * Hsz + j];
    }
    float mean = blockReduceSum128(x[0] + x[1] + x[2], red) * (1.f / Hsz);
    float sq = 0.f;
    #pragma unroll
    for (int i = 0; i < 3; i++) { float d = x[i] - mean; sq += d * d; }
    float var = blockReduceSum128(sq, red) * (1.f / Hsz);
    float inv = rsqrtf(var + 1e-12f);
    #pragma unroll
    for (int i = 0; i < 3; i++) {
        int j = tid + i * 128;
        float o = g[j] * (x[i] - mean) * inv + b[j];
        g_h[(size_t)row * Hsz + j] = o;
        g_hh[(size_t)row * Hsz + j] = __float2half_rn(o);
    }
}

// ---------------- FP16 tensor-core GEMM (128x128 block, 64x64 warp tile) -------
struct HgemmSmem {
    __half As[2][128][40];
    __half Bs[2][128][40];
};

__device__ __forceinline__ void hgemm_body(
        const __half* __restrict__ A, const __half* __restrict__ Wt,
        const float* __restrict__ bias, float* __restrict__ Cf, __half* __restrict__ Ch,
        int N, int K, int act, int bx, int by, HgemmSmem& sm) {
    const int t = threadIdx.x;     // 128
    const int lane = t & 31, warp = t >> 5;
    const int kk = lane & 3, gr = lane >> 2;
    const int mw = (warp >> 1) * 64;
    const int nw = (warp & 1) * 64;
    const int br = by * 128, bc = bx * 128;

    const int rbase = t >> 2, cc = t & 3;
    const __half* Ag = A + (size_t)(br + rbase) * K + cc * 8;
    const __half* Bg = Wt + (size_t)(bc + rbase) * K + cc * 8;

    float acc[4][8][4] = {};
    const int T = K >> 5;

    #define HGL(k0, buf) do { \
        _Pragma("unroll") \
        for (int i_ = 0; i_ < 4; i_++) { \
            cpasync16(&sm.As[buf][rbase + 32*i_][cc*8], Ag + (size_t)(32*i_) * K + (k0)); \
            cpasync16(&sm.Bs[buf][rbase + 32*i_][cc*8], Bg + (size_t)(32*i_) * K + (k0)); \
        } \
        cp_commit(); \
    } while (0)

    HGL(0, 0);
    int buf = 0;
    for (int tt = 0; tt < T; tt++) {
        cp_wait0();
        __syncthreads();
        if (tt + 1 < T) HGL((tt + 1) << 5, buf ^ 1);
        #pragma unroll
        for (int ks = 0; ks < 32; ks += 16) {
            unsigned a[4][4], b[8][2];
            #pragma unroll
            for (int mt = 0; mt < 4; mt++) {
                int m = mw + mt * 16 + gr;
                a[mt][0] = *(const unsigned*)&sm.As[buf][m][ks + 2*kk];
                a[mt][1] = *(const unsigned*)&sm.As[buf][m + 8][ks + 2*kk];
                a[mt][2] = *(const unsigned*)&sm.As[buf][m][ks + 2*kk + 8];
                a[mt][3] = *(const unsigned*)&sm.As[buf][m + 8][ks + 2*kk + 8];
            }
            #pragma unroll
            for (int nt = 0; nt < 8; nt++) {
                int n = nw + nt * 8 + gr;
                b[nt][0] = *(const unsigned*)&sm.Bs[buf][n][ks + 2*kk];
                b[nt][1] = *(const unsigned*)&sm.Bs[buf][n][ks + 2*kk + 8];
            }
            #pragma unroll
            for (int mt = 0; mt < 4; mt++)
                #pragma unroll
                for (int nt = 0; nt < 8; nt++)
                    MMA_F16(acc[mt][nt], a[mt], b[nt]);
        }
        __syncthreads();
        buf ^= 1;
    }
    #undef HGL

    #pragma unroll
    for (int nt = 0; nt < 8; nt++) {
        int col = bc + nw + nt * 8 + 2 * kk;
        float b0 = bias[col], b1 = bias[col + 1];
        #pragma unroll
        for (int mt = 0; mt < 4; mt++) {
            int row = br + mw + mt * 16 + gr;
            float v0 = acc[mt][nt][0] + b0, v1 = acc[mt][nt][1] + b1;
            float v2 = acc[mt][nt][2] + b0, v3 = acc[mt][nt][3] + b1;
            if (act == 1) {
                v0 = 0.5f * v0 * (1.f + erff(v0 * 0.70710678118654752f));
                v1 = 0.5f * v1 * (1.f + erff(v1 * 0.70710678118654752f));
                v2 = 0.5f * v2 * (1.f + erff(v2 * 0.70710678118654752f));
                v3 = 0.5f * v3 * (1.f + erff(v3 * 0.70710678118654752f));
            }
            if (Ch) {
                *reinterpret_cast<__half2*>(&Ch[(size_t)row * N + col]) =
                    __floats2half2_rn(v0, v1);
                *reinterpret_cast<__half2*>(&Ch[(size_t)(row + 8) * N + col]) =
                    __floats2half2_rn(v2, v3);
            } else {
                *reinterpret_cast<float2*>(&Cf[(size_t)row * N + col]) = make_float2(v0, v1);
                *reinterpret_cast<float2*>(&Cf[(size_t)(row + 8) * N + col]) = make_float2(v2, v3);
            }
        }
    }
}

__global__ __launch_bounds__(128, 2) void hgemm_kernel(
        const __half* __restrict__ A, const __half* __restrict__ Wt,
        const float* __restrict__ bias, float* __restrict__ Cf, __half* __restrict__ Ch,
        int N, int K, int act) {
    __shared__ HgemmSmem sm;
    hgemm_body(A, Wt, bias, Cf, Ch, N, K, act, blockIdx.x, blockIdx.y, sm);
}

__global__ __launch_bounds__(128, 2) void hgemm_qkv_kernel(
        const __half* __restrict__ A,
        const __half* __restrict__ Wtq, const __half* __restrict__ Wtk, const __half* __restrict__ Wtv,
        const float* __restrict__ bq, const float* __restrict__ bk, const float* __restrict__ bv,
        __half* __restrict__ Cq, __half* __restrict__ Ck, __half* __restrict__ Cv) {
    __shared__ HgemmSmem sm;
    const __half* Ws[3] = {Wtq, Wtk, Wtv};
    const float* bs[3] = {bq, bk, bv};
    __half* Cs[3] = {Cq, Ck, Cv};
    int z = blockIdx.z;
    hgemm_body(A, Ws[z], bs[z], (float*)0, Cs[z], Hsz, Hsz, 0, blockIdx.x, blockIdx.y, sm);
}

// ---------------- fp16 tensor-core flash attention (2 CTAs/SM — proven) --------
#define ATTN_SMEM_BYTES (256*40*2 + 32*264*2 + 8*32*40*2 + 256*4)
#define SCL 0.17677669529663688f

__global__ __launch_bounds__(256, 2) void attn_mma_kernel(
        const __half* __restrict__ q, const __half* __restrict__ k,
        const __half* __restrict__ v, const int* __restrict__ mask,
        __half* __restrict__ ctx) {
    extern __shared__ char smraw[];
    __half* Ksh = reinterpret_cast<__half*>(smraw);              // [256][40]
    __half* Vth = Ksh + 256*40;                                  // [32][264]
    __half* Pwh = Vth + 32*264;                                  // [8][32][40]
    float*  bi  = reinterpret_cast<float*>(Pwh + 8*32*40);       // [256]

    const int h = blockIdx.x, b = blockIdx.y;
    const int tid = threadIdx.x, lane = tid & 31, w = tid >> 5;
    const int gr = lane >> 2, kk = lane & 3;

    for (int idx = tid; idx < 256*32; idx += 256) {
        int key = idx >> 5, d = idx & 31;
        size_t gi = (size_t)(b*Ssz + key)*Hsz + h*DHs + d;
        Ksh[key*40 + d] = k[gi];
        Vth[d*264 + key] = v[gi];
    }
    bi[tid] = (1.f - (float)mask[b*Ssz + tid]) * -1e9f;
    __syncthreads();

    unsigned aq[2][2][4];
    const int qrow0 = b*Ssz + w*32 + gr;
    #pragma unroll
    for (int mt = 0; mt < 2; mt++)
        #pragma unroll
        for (int kt = 0; kt < 2; kt++) {
            const __half* qp = q + (size_t)(qrow0 + mt*16)*Hsz + h*DHs + kt*16 + 2*kk;
            aq[mt][kt][0] = *(const unsigned*)qp;
            aq[mt][kt][1] = *(const unsigned*)(qp + 8*(size_t)Hsz);
            aq[mt][kt][2] = *(const unsigned*)(qp + 8);
            aq[mt][kt][3] = *(const unsigned*)(qp + 8*(size_t)Hsz + 8);
        }

    float m_[2][2] = {{-1e30f, -1e30f}, {-1e30f, -1e30f}};
    float l_[2][2] = {};
    float o[2][4][4] = {};
    __half* pw = Pwh + w*(32*40);

    for (int t = 0; t < 8; t++) {
        const int kb = t*32;
        float s[2][4][4] = {};
        #pragma unroll
        for (int kt = 0; kt < 2; kt++) {
            unsigned bf[4][2];
            #pragma unroll
            for (int nt = 0; nt < 4; nt++) {
                const __half* kp = &Ksh[(kb + nt*8 + gr)*40 + kt*16 + 2*kk];
                bf[nt][0] = *(const unsigned*)kp;
                bf[nt][1] = *(const unsigned*)(kp + 8);
            }
            #pragma unroll
            for (int mt = 0; mt < 2; mt++)
                #pragma unroll
                for (int nt = 0; nt < 4; nt++)
                    MMA_F16(s[mt][nt], aq[mt][kt], bf[nt]);
        }
        #pragma unroll
        for (int nt = 0; nt < 4; nt++) {
            float2 bv = *reinterpret_cast<const float2*>(&bi[kb + nt*8 + 2*kk]);
            #pragma unroll
            for (int mt = 0; mt < 2; mt++) {
                s[mt][nt][0] = s[mt][nt][0]*SCL + bv.x;
                s[mt][nt][1] = s[mt][nt][1]*SCL + bv.y;
                s[mt][nt][2] = s[mt][nt][2]*SCL + bv.x;
                s[mt][nt][3] = s[mt][nt][3]*SCL + bv.y;
            }
        }
        #pragma unroll
        for (int mt = 0; mt < 2; mt++) {
            #pragma unroll
            for (int hf = 0; hf < 2; hf++) {
                float tm = -1e30f;
                #pragma unroll
                for (int nt = 0; nt < 4; nt++)
                    tm = fmaxf(tm, fmaxf(s[mt][nt][2*hf], s[mt][nt][2*hf+1]));
                tm = fmaxf(tm, __shfl_xor_sync(0xffffffffu, tm, 1));
                tm = fmaxf(tm, __shfl_xor_sync(0xffffffffu, tm, 2));
                float nm = fmaxf(m_[mt][hf], tm);
                float corr = __expf(m_[mt][hf] - nm);
                m_[mt][hf] = nm;
                float rs = 0.f;
                #pragma unroll
                for (int nt = 0; nt < 4; nt++) {
                    float p0 = __expf(s[mt][nt][2*hf] - nm);
                    float p1 = __expf(s[mt][nt][2*hf+1] - nm);
                    s[mt][nt][2*hf] = p0; s[mt][nt][2*hf+1] = p1;
                    rs += p0 + p1;
                    o[mt][nt][2*hf]   *= corr;
                    o[mt][nt][2*hf+1] *= corr;
                }
                rs += __shfl_xor_sync(0xffffffffu, rs, 1);
                rs += __shfl_xor_sync(0xffffffffu, rs, 2);
                l_[mt][hf] = l_[mt][hf]*corr + rs;
            }
        }
        #pragma unroll
        for (int mt = 0; mt < 2; mt++)
            #pragma unroll
            for (int nt = 0; nt < 4; nt++) {
                *reinterpret_cast<__half2*>(&pw[(mt*16+gr)*40 + nt*8 + 2*kk]) =
                    __floats2half2_rn(s[mt][nt][0], s[mt][nt][1]);
                *reinterpret_cast<__half2*>(&pw[(mt*16+gr+8)*40 + nt*8 + 2*kk]) =
                    __floats2half2_rn(s[mt][nt][2], s[mt][nt][3]);
            }
        __syncwarp();
        #pragma unroll
        for (int kt = 0; kt < 2; kt++) {
            unsigned ap[2][4];
            #pragma unroll
            for (int mt = 0; mt < 2; mt++) {
                const __half* pp = &pw[(mt*16+gr)*40 + kt*16 + 2*kk];
                ap[mt][0] = *(const unsigned*)pp;
                ap[mt][1] = *(const unsigned*)(pp + 8*40);
                ap[mt][2] = *(const unsigned*)(pp + 8);
                ap[mt][3] = *(const unsigned*)(pp + 8*40 + 8);
            }
            unsigned bf[4][2];
            #pragma unroll
            for (int nt = 0; nt < 4; nt++) {
                const __half* vp = &Vth[(nt*8+gr)*264 + kb + kt*16 + 2*kk];
                bf[nt][0] = *(const unsigned*)vp;
                bf[nt][1] = *(const unsigned*)(vp + 8);
            }
            #pragma unroll
            for (int mt = 0; mt < 2; mt++)
                #pragma unroll
                for (int nt = 0; nt < 4; nt++)
                    MMA_F16(o[mt][nt], ap[mt], bf[nt]);
        }
        __syncwarp();
    }

    #pragma unroll
    for (int mt = 0; mt < 2; mt++) {
        float i0 = 1.f / l_[mt][0], i1 = 1.f / l_[mt][1];
        #pragma unroll
        for (int nt = 0; nt < 4; nt++) {
            size_t base = (size_t)(qrow0 + mt*16)*Hsz + h*DHs + nt*8 + 2*kk;
            *reinterpret_cast<__half2*>(&ctx[base]) =
                __floats2half2_rn(o[mt][nt][0]*i0, o[mt][nt][1]*i0);
            *reinterpret_cast<__half2*>(&ctx[base + 8*(size_t)Hsz]) =
                __floats2half2_rn(o[mt][nt][2]*i1, o[mt][nt][3]*i1);
        }
    }
}

// ---------------- residual + LN (warp per row; half delta; writes f32 + half) --
__global__ __launch_bounds__(256) void residual_ln_kernel(
        const __half* __restrict__ delta,
        const float* __restrict__ g, const float* __restrict__ b) {
    const int lane = threadIdx.x & 31, w = threadIdx.x >> 5;
    const int row = blockIdx.x * 8 + w;
    const float4* hp = reinterpret_cast<const float4*>(g_h + (size_t)row * Hsz);
    const __half2* dp = reinterpret_cast<const __half2*>(delta + (size_t)row * Hsz);
    float4 x[3];
    float sum = 0.f;
    #pragma unroll
    for (int i = 0; i < 3; i++) {
        int j = lane + i * 32;
        float4 hv = hp[j];
        float2 d0 = __half22float2(dp[2*j]);
        float2 d1 = __half22float2(dp[2*j + 1]);
        x[i] = make_float4(hv.x + d0.x, hv.y + d0.y, hv.z + d1.x, hv.w + d1.y);
        sum += x[i].x + x[i].y + x[i].z + x[i].w;
    }
    #pragma unroll
    for (int o = 16; o > 0; o >>= 1) sum += __shfl_xor_sync(0xffffffffu, sum, o);
    float mean = sum * (1.f / Hsz);
    float sq = 0.f;
    #pragma unroll
    for (int i = 0; i < 3; i++) {
        float dx = x[i].x - mean, dy = x[i].y - mean, dz = x[i].z - mean, dw = x[i].w - mean;
        sq += dx*dx + dy*dy + dz*dz + dw*dw;
    }
    #pragma unroll
    for (int o = 16; o > 0; o >>= 1) sq += __shfl_xor_sync(0xffffffffu, sq, o);
    float inv = rsqrtf(sq * (1.f / Hsz) + 1e-12f);
    float4* op = reinterpret_cast<float4*>(g_h + (size_t)row * Hsz);
    __half2* oph = reinterpret_cast<__half2*>(g_hh + (size_t)row * Hsz);
    const float4* gp = reinterpret_cast<const float4*>(g);
    const float4* bp = reinterpret_cast<const float4*>(b);
    #pragma unroll
    for (int i = 0; i < 3; i++) {
        int j = lane + i * 32;
        float4 gv = gp[j], bv = bp[j];
        float4 r = make_float4(gv.x * (x[i].x - mean) * inv + bv.x,
                               gv.y * (x[i].y - mean) * inv + bv.y,
                               gv.z * (x[i].z - mean) * inv + bv.z,
                               gv.w * (x[i].w - mean) * inv + bv.w);
        op[j] = r;
        oph[2*j]     = __floats2half2_rn(r.x, r.y);
        oph[2*j + 1] = __floats2half2_rn(r.z, r.w);
    }
}

// ---------------- offramp ------------------------------------------------------
__global__ void offramp_kernel(const float* __restrict__ Wr, const float* __restrict__ br,
                               int layer) {
    __shared__ float w[Hsz];
    int tid = threadIdx.x;  // 128
    #pragma unroll
    for (int i = 0; i < 3; i++) w[tid + i * 128] = Wr[layer * Hsz + tid + i * 128];
    __syncthreads();
    int b = tid;
    const float* hr = g_h + (size_t)(b * Ssz) * Hsz;
    float l = br[layer];
    for (int kk = 0; kk < Hsz; kk++) l = fmaf(hr[kk], w[kk], l);
    float lsp = (l > 0.f) ? -log1pf(expf(-l)) : (l - log1pf(expf(l)));
    float lsn = (l < 0.f) ? -log1pf(expf(l)) : (-l - log1pf(expf(-l)));
    float p = 1.f / (1.f + expf(-l));
    float ent = -(p * lsp + (1.f - p) * lsn);
    if (g_active[b] && ent < 0.1f) {
        g_scores[b] = l; g_exitl[b] = layer; g_active[b] = 0;
    }
}

// ---------------- pooler -------------------------------------------------------
__global__ void pooler_kernel(const float* __restrict__ Wp, const float* __restrict__ bp) {
    __shared__ float hr[Hsz];
    int b = blockIdx.x, tid = threadIdx.x;   // 384 threads
    hr[tid] = g_h[(size_t)(b * Ssz) * Hsz + tid];
    __syncthreads();
    float acc = bp[tid];
    for (int kk = 0; kk < Hsz; kk++) acc = fmaf(hr[kk], Wp[kk * Hsz + tid], acc);
    g_pooled[b * Hsz + tid] = tanhf(acc);
}

// ---------------- final classifier + output ------------------------------------
__global__ void final_kernel(const float* __restrict__ Wc, const float* __restrict__ bc,
                             float* __restrict__ out, int out_size) {
    __shared__ int counts[8];
    int tid = threadIdx.x;  // 128
    if (tid < 8) counts[tid] = 0;
    __syncthreads();
    int b = tid;
    float acc = bc[0];
    for (int kk = 0; kk < Hsz; kk++) acc = fmaf(g_pooled[b * Hsz + kk], Wc[kk], acc);
    float sc; int el;
    if (g_active[b]) { sc = acc; el = NOFF; }
    else             { sc = g_scores[b]; el = g_exitl[b]; }
    atomicAdd(&counts[el], 1);
    __syncthreads();
    out[b] = sc;
    out[Bsz + b] = (float)el;
    if (tid < NOFF + 1) out[2 * Bsz + tid] = (float)counts[tid];
    for (int i = 2 * Bsz + NOFF + 1 + tid; i < out_size; i += 128) out[i] = 0.f;
}

// ---------------- launch -------------------------------------------------------
extern "C" void kernel_launch(void* const* d_in, const int* in_sizes, int n_in,
                              void* d_out, int out_size) {
    (void)in_sizes; (void)n_in;
    const int*   input_ids      = (const int*)d_in[0];
    const int*   attention_mask = (const int*)d_in[1];
    const int*   token_type_ids = (const int*)d_in[2];
    const float* word_emb = (const float*)d_in[3];
    const float* pos_emb  = (const float*)d_in[4];
    const float* type_emb = (const float*)d_in[5];
    const float* emb_ln_g = (const float*)d_in[6];
    const float* emb_ln_b = (const float*)d_in[7];
    const float* Wq = (const float*)d_in[8];  const float* bq = (const float*)d_in[9];
    const float* Wk = (const float*)d_in[10]; const float* bk = (const float*)d_in[11];
    const float* Wv = (const float*)d_in[12]; const float* bv = (const float*)d_in[13];
    const float* Wo = (const float*)d_in[14]; const float* bo = (const float*)d_in[15];
    const float* ln1_g = (const float*)d_in[16]; const float* ln1_b = (const float*)d_in[17];
    const float* Wi = (const float*)d_in[18]; const float* bi = (const float*)d_in[19];
    const float* Wfo = (const float*)d_in[20]; const float* bfo = (const float*)d_in[21];
    const float* ln2_g = (const float*)d_in[22]; const float* ln2_b = (const float*)d_in[23];
    const float* Wp = (const float*)d_in[24]; const float* bp = (const float*)d_in[25];
    const float* Wc = (const float*)d_in[26]; const float* bc = (const float*)d_in[27];
    const float* Wr = (const float*)d_in[28]; const float* br = (const float*)d_in[29];

    __half *hhp, *qh, *kh, *vh, *ctxh, *tmph, *ffh;
    __half *whq, *whk, *whv, *who, *whi, *whfo;
    cudaGetSymbolAddress((void**)&hhp, g_hh);
    cudaGetSymbolAddress((void**)&qh, g_qh);
    cudaGetSymbolAddress((void**)&kh, g_kh);
    cudaGetSymbolAddress((void**)&vh, g_vh);
    cudaGetSymbolAddress((void**)&ctxh, g_ctxh);
    cudaGetSymbolAddress((void**)&tmph, g_tmph);
    cudaGetSymbolAddress((void**)&ffh, g_ffh);
    cudaGetSymbolAddress((void**)&whq, g_whq);
    cudaGetSymbolAddress((void**)&whk, g_whk);
    cudaGetSymbolAddress((void**)&whv, g_whv);
    cudaGetSymbolAddress((void**)&who, g_who);
    cudaGetSymbolAddress((void**)&whi, g_whi);
    cudaGetSymbolAddress((void**)&whfo, g_whfo);

    cudaFuncSetAttribute(attn_mma_kernel,
                         cudaFuncAttributeMaxDynamicSharedMemorySize, ATTN_SMEM_BYTES);

    init_state_kernel<<<1, 128>>>();
    embed_ln_kernel<<<ROWS, 128>>>(input_ids, token_type_ids, word_emb, pos_emb, type_emb,
                                   emb_ln_g, emb_ln_b);

    dim3 tb(32, 8);
    transpose_h_kernel<<<dim3(Hsz/32, Hsz/32, Lyr), tb>>>(Wq,  whq,  Hsz, Hsz);
    transpose_h_kernel<<<dim3(Hsz/32, Hsz/32, Lyr), tb>>>(Wk,  whk,  Hsz, Hsz);
    transpose_h_kernel<<<dim3(Hsz/32, Hsz/32, Lyr), tb>>>(Wv,  whv,  Hsz, Hsz);
    transpose_h_kernel<<<dim3(Hsz/32, Hsz/32, Lyr), tb>>>(Wo,  who,  Hsz, Hsz);
    transpose_h_kernel<<<dim3(Fsz/32, Hsz/32, Lyr), tb>>>(Wi,  whi,  Hsz, Fsz);
    transpose_h_kernel<<<dim3(Hsz/32, Fsz/32, Lyr), tb>>>(Wfo, whfo, Fsz, Hsz);

    dim3 gHH(Hsz / 128, ROWS / 128);          // (3, 256)
    dim3 gQKV(Hsz / 128, ROWS / 128, 3);      // (3, 256, 3)
    dim3 gHF(Fsz / 128, ROWS / 128);          // (12, 256)

    for (int i = 0; i < Lyr; i++) {
        hgemm_qkv_kernel<<<gQKV, 128>>>(hhp,
                    whq + (size_t)i * Hsz * Hsz, whk + (size_t)i * Hsz * Hsz,
                    whv + (size_t)i * Hsz * Hsz,
                    bq + i * Hsz, bk + i * Hsz, bv + i * Hsz,
                    qh, kh, vh);
        attn_mma_kernel<<<dim3(NHs, Bsz), 256, ATTN_SMEM_BYTES>>>(qh, kh, vh,
                                                                  attention_mask, ctxh);
        hgemm_kernel<<<gHH, 128>>>(ctxh, who + (size_t)i * Hsz * Hsz,
                                   bo + i * Hsz, (float*)0, tmph, Hsz, Hsz, 0);
        residual_ln_kernel<<<ROWS / 8, 256>>>(tmph, ln1_g + i * Hsz, ln1_b + i * Hsz);
        hgemm_kernel<<<gHF, 128>>>(hhp, whi + (size_t)i * Hsz * Fsz,
                                   bi + i * Fsz, (float*)0, ffh, Fsz, Hsz, 1);
        hgemm_kernel<<<gHH, 128>>>(ffh, whfo + (size_t)i * Fsz * Hsz,
                                   bfo + i * Hsz, (float*)0, tmph, Hsz, Fsz, 0);
        residual_ln_kernel<<<ROWS / 8, 256>>>(tmph, ln2_g + i * Hsz, ln2_b + i * Hsz);
        if (i < NOFF) {
            offramp_kernel<<<1, 128>>>(Wr, br, i);
        }
    }
    pooler_kernel<<<Bsz, Hsz>>>(Wp, bp);
    final_kernel<<<1, 128>>>(Wc, bc, (float*)d_out, out_size);
}

// round 15
// speedup vs baseline: 1.1106x; 1.0689x over previous
#include <cuda_runtime.h>
#include <cuda_fp16.h>
#include <math.h>

#define Bsz 128
#define Ssz 256
#define Hsz 384
#define NHs 12
#define DHs 32
#define Fsz 1536
#define Lyr 6
#define NOFF 5
#define ROWS (Bsz*Ssz)   /* 32768 */

// ---------------- scratch (static device globals; no allocation) --------------
__device__ __half g_hh[ROWS*Hsz];        // residual stream h (half)
__device__ __half g_qh[ROWS*Hsz];
__device__ __half g_kh[ROWS*Hsz];
__device__ __half g_vh[ROWS*Hsz];
__device__ __half g_ctxh[ROWS*Hsz];      // attention output (half)
__device__ __half g_tmph[ROWS*Hsz];      // residual delta (half)
__device__ __half g_ffh[ROWS*Fsz];       // FFN intermediate (half)
__device__ float  g_pooled[Bsz*Hsz];
__device__ int    g_active[Bsz];
__device__ float  g_scores[Bsz];
__device__ int    g_exitl[Bsz];
// transposed half weights: Wt[n][k] = (half)W[k][n]
__device__ __half g_whq[Lyr*Hsz*Hsz];
__device__ __half g_whk[Lyr*Hsz*Hsz];
__device__ __half g_whv[Lyr*Hsz*Hsz];
__device__ __half g_who[Lyr*Hsz*Hsz];
__device__ __half g_whi[Lyr*Hsz*Fsz];
__device__ __half g_whfo[Lyr*Fsz*Hsz];

// ---------------- helpers ------------------------------------------------------
__device__ __forceinline__ float blockReduceSum128(float val, float* smem4) {
    int lane = threadIdx.x & 31, warp = threadIdx.x >> 5;
    #pragma unroll
    for (int o = 16; o > 0; o >>= 1) val += __shfl_down_sync(0xffffffffu, val, o);
    if (lane == 0) smem4[warp] = val;
    __syncthreads();
    float v = (threadIdx.x < 4) ? smem4[threadIdx.x] : 0.f;
    if (warp == 0) {
        v += __shfl_down_sync(0xffffffffu, v, 2);
        v += __shfl_down_sync(0xffffffffu, v, 1);
        if (lane == 0) smem4[0] = v;
    }
    __syncthreads();
    float r = smem4[0];
    __syncthreads();
    return r;
}

__device__ __forceinline__ void cpasync16(void* dst, const void* src) {
    unsigned sa = (unsigned)__cvta_generic_to_shared(dst);
    asm volatile("cp.async.cg.shared.global [%0], [%1], 16;\n" :: "r"(sa), "l"(src));
}
__device__ __forceinline__ void cp_commit() { asm volatile("cp.async.commit_group;\n"); }
__device__ __forceinline__ void cp_wait0()  { asm volatile("cp.async.wait_group 0;\n"); }

#define MMA_F16(d, a, bfr) \
    asm volatile("mma.sync.aligned.m16n8k16.row.col.f32.f16.f16.f32 " \
        "{%0,%1,%2,%3}, {%4,%5,%6,%7}, {%8,%9}, {%0,%1,%2,%3};" \
        : "+f"((d)[0]), "+f"((d)[1]), "+f"((d)[2]), "+f"((d)[3]) \
        : "r"((a)[0]), "r"((a)[1]), "r"((a)[2]), "r"((a)[3]), \
          "r"((bfr)[0]), "r"((bfr)[1]))

// ---------------- state init ---------------------------------------------------
__global__ void init_state_kernel() {
    int t = threadIdx.x;
    if (t < Bsz) { g_active[t] = 1; g_scores[t] = 0.f; g_exitl[t] = 0; }
}

// ---------------- weight transpose + fp16 convert: dst[n][k] = (half)src[k][n] -
__global__ void transpose_h_kernel(const float* __restrict__ src, __half* __restrict__ dst,
                                   int K, int N) {
    __shared__ float tile[32][33];
    const float* s = src + (size_t)blockIdx.z * K * N;
    __half* d = dst + (size_t)blockIdx.z * K * N;
    int n0 = blockIdx.x * 32, k0 = blockIdx.y * 32;
    #pragma unroll
    for (int i = threadIdx.y; i < 32; i += 8)
        tile[i][threadIdx.x] = s[(size_t)(k0 + i) * N + n0 + threadIdx.x];
    __syncthreads();
    #pragma unroll
    for (int i = threadIdx.y; i < 32; i += 8)
        d[(size_t)(n0 + i) * K + k0 + threadIdx.x] = __float2half_rn(tile[threadIdx.x][i]);
}

// ---------------- embeddings + LN (writes half h) ------------------------------
__global__ void embed_ln_kernel(const int* __restrict__ ids, const int* __restrict__ tts,
                                const float* __restrict__ we, const float* __restrict__ pe,
                                const float* __restrict__ te, const float* __restrict__ g,
                                const float* __restrict__ b) {
    __shared__ float red[4];
    int row = blockIdx.x, s = row & (Ssz - 1), tid = threadIdx.x;
    int id = ids[row], tt = tts[row];
    float x[3];
    #pragma unroll
    for (int i = 0; i < 3; i++) {
        int j = tid + i * 128;
        x[i] = we[id * Hsz + j] + pe[s * Hsz + j] + te[tt * Hsz + j];
    }
    float mean = blockReduceSum128(x[0] + x[1] + x[2], red) * (1.f / Hsz);
    float sq = 0.f;
    #pragma unroll
    for (int i = 0; i < 3; i++) { float d = x[i] - mean; sq += d * d; }
    float var = blockReduceSum128(sq, red) * (1.f / Hsz);
    float inv = rsqrtf(var + 1e-12f);
    #pragma unroll
    for (int i = 0; i < 3; i++) {
        int j = tid + i * 128;
        float o = g[j] * (x[i] - mean) * inv + b[j];
        g_hh[(size_t)row * Hsz + j] = __float2half_rn(o);
    }
}

// ---------------- FP16 tensor-core GEMM (128x128 block, 64x64 warp tile) -------
struct HgemmSmem {
    __half As[2][128][40];
    __half Bs[2][128][40];
};

__device__ __forceinline__ void hgemm_body(
        const __half* __restrict__ A, const __half* __restrict__ Wt,
        const float* __restrict__ bias, __half* __restrict__ Ch,
        int N, int K, int act, int bx, int by, HgemmSmem& sm) {
    const int t = threadIdx.x;     // 128
    const int lane = t & 31, warp = t >> 5;
    const int kk = lane & 3, gr = lane >> 2;
    const int mw = (warp >> 1) * 64;
    const int nw = (warp & 1) * 64;
    const int br = by * 128, bc = bx * 128;

    const int rbase = t >> 2, cc = t & 3;
    const __half* Ag = A + (size_t)(br + rbase) * K + cc * 8;
    const __half* Bg = Wt + (size_t)(bc + rbase) * K + cc * 8;

    float acc[4][8][4] = {};
    const int T = K >> 5;

    #define HGL(k0, buf) do { \
        _Pragma("unroll") \
        for (int i_ = 0; i_ < 4; i_++) { \
            cpasync16(&sm.As[buf][rbase + 32*i_][cc*8], Ag + (size_t)(32*i_) * K + (k0)); \
            cpasync16(&sm.Bs[buf][rbase + 32*i_][cc*8], Bg + (size_t)(32*i_) * K + (k0)); \
        } \
        cp_commit(); \
    } while (0)

    HGL(0, 0);
    int buf = 0;
    for (int tt = 0; tt < T; tt++) {
        cp_wait0();
        __syncthreads();
        if (tt + 1 < T) HGL((tt + 1) << 5, buf ^ 1);
        #pragma unroll
        for (int ks = 0; ks < 32; ks += 16) {
            unsigned a[4][4], b[8][2];
            #pragma unroll
            for (int mt = 0; mt < 4; mt++) {
                int m = mw + mt * 16 + gr;
                a[mt][0] = *(const unsigned*)&sm.As[buf][m][ks + 2*kk];
                a[mt][1] = *(const unsigned*)&sm.As[buf][m + 8][ks + 2*kk];
                a[mt][2] = *(const unsigned*)&sm.As[buf][m][ks + 2*kk + 8];
                a[mt][3] = *(const unsigned*)&sm.As[buf][m + 8][ks + 2*kk + 8];
            }
            #pragma unroll
            for (int nt = 0; nt < 8; nt++) {
                int n = nw + nt * 8 + gr;
                b[nt][0] = *(const unsigned*)&sm.Bs[buf][n][ks + 2*kk];
                b[nt][1] = *(const unsigned*)&sm.Bs[buf][n][ks + 2*kk + 8];
            }
            #pragma unroll
            for (int mt = 0; mt < 4; mt++)
                #pragma unroll
                for (int nt = 0; nt < 8; nt++)
                    MMA_F16(acc[mt][nt], a[mt], b[nt]);
        }
        __syncthreads();
        buf ^= 1;
    }
    #undef HGL

    #pragma unroll
    for (int nt = 0; nt < 8; nt++) {
        int col = bc + nw + nt * 8 + 2 * kk;
        float b0 = bias[col], b1 = bias[col + 1];
        #pragma unroll
        for (int mt = 0; mt < 4; mt++) {
            int row = br + mw + mt * 16 + gr;
            float v0 = acc[mt][nt][0] + b0, v1 = acc[mt][nt][1] + b1;
            float v2 = acc[mt][nt][2] + b0, v3 = acc[mt][nt][3] + b1;
            if (act == 1) {
                v0 = 0.5f * v0 * (1.f + erff(v0 * 0.70710678118654752f));
                v1 = 0.5f * v1 * (1.f + erff(v1 * 0.70710678118654752f));
                v2 = 0.5f * v2 * (1.f + erff(v2 * 0.70710678118654752f));
                v3 = 0.5f * v3 * (1.f + erff(v3 * 0.70710678118654752f));
            }
            *reinterpret_cast<__half2*>(&Ch[(size_t)row * N + col]) =
                __floats2half2_rn(v0, v1);
            *reinterpret_cast<__half2*>(&Ch[(size_t)(row + 8) * N + col]) =
                __floats2half2_rn(v2, v3);
        }
    }
}

__global__ __launch_bounds__(128, 2) void hgemm_kernel(
        const __half* __restrict__ A, const __half* __restrict__ Wt,
        const float* __restrict__ bias, __half* __restrict__ Ch,
        int N, int K, int act) {
    __shared__ HgemmSmem sm;
    hgemm_body(A, Wt, bias, Ch, N, K, act, blockIdx.x, blockIdx.y, sm);
}

__global__ __launch_bounds__(128, 2) void hgemm_qkv_kernel(
        const __half* __restrict__ A,
        const __half* __restrict__ Wtq, const __half* __restrict__ Wtk, const __half* __restrict__ Wtv,
        const float* __restrict__ bq, const float* __restrict__ bk, const float* __restrict__ bv,
        __half* __restrict__ Cq, __half* __restrict__ Ck, __half* __restrict__ Cv) {
    __shared__ HgemmSmem sm;
    const __half* Ws[3] = {Wtq, Wtk, Wtv};
    const float* bs[3] = {bq, bk, bv};
    __half* Cs[3] = {Cq, Ck, Cv};
    int z = blockIdx.z;
    hgemm_body(A, Ws[z], bs[z], Cs[z], Hsz, Hsz, 0, blockIdx.x, blockIdx.y, sm);
}

// ---------------- fp16 tensor-core flash attention (2 CTAs/SM — proven) --------
#define ATTN_SMEM_BYTES (256*40*2 + 32*264*2 + 8*32*40*2 + 256*4)
#define SCL 0.17677669529663688f

__global__ __launch_bounds__(256, 2) void attn_mma_kernel(
        const __half* __restrict__ q, const __half* __restrict__ k,
        const __half* __restrict__ v, const int* __restrict__ mask,
        __half* __restrict__ ctx) {
    extern __shared__ char smraw[];
    __half* Ksh = reinterpret_cast<__half*>(smraw);              // [256][40]
    __half* Vth = Ksh + 256*40;                                  // [32][264]
    __half* Pwh = Vth + 32*264;                                  // [8][32][40]
    float*  bi  = reinterpret_cast<float*>(Pwh + 8*32*40);       // [256]

    const int h = blockIdx.x, b = blockIdx.y;
    const int tid = threadIdx.x, lane = tid & 31, w = tid >> 5;
    const int gr = lane >> 2, kk = lane & 3;

    for (int idx = tid; idx < 256*32; idx += 256) {
        int key = idx >> 5, d = idx & 31;
        size_t gi = (size_t)(b*Ssz + key)*Hsz + h*DHs + d;
        Ksh[key*40 + d] = k[gi];
        Vth[d*264 + key] = v[gi];
    }
    bi[tid] = (1.f - (float)mask[b*Ssz + tid]) * -1e9f;
    __syncthreads();

    unsigned aq[2][2][4];
    const int qrow0 = b*Ssz + w*32 + gr;
    #pragma unroll
    for (int mt = 0; mt < 2; mt++)
        #pragma unroll
        for (int kt = 0; kt < 2; kt++) {
            const __half* qp = q + (size_t)(qrow0 + mt*16)*Hsz + h*DHs + kt*16 + 2*kk;
            aq[mt][kt][0] = *(const unsigned*)qp;
            aq[mt][kt][1] = *(const unsigned*)(qp + 8*(size_t)Hsz);
            aq[mt][kt][2] = *(const unsigned*)(qp + 8);
            aq[mt][kt][3] = *(const unsigned*)(qp + 8*(size_t)Hsz + 8);
        }

    float m_[2][2] = {{-1e30f, -1e30f}, {-1e30f, -1e30f}};
    float l_[2][2] = {};
    float o[2][4][4] = {};
    __half* pw = Pwh + w*(32*40);

    for (int t = 0; t < 8; t++) {
        const int kb = t*32;
        float s[2][4][4] = {};
        #pragma unroll
        for (int kt = 0; kt < 2; kt++) {
            unsigned bf[4][2];
            #pragma unroll
            for (int nt = 0; nt < 4; nt++) {
                const __half* kp = &Ksh[(kb + nt*8 + gr)*40 + kt*16 + 2*kk];
                bf[nt][0] = *(const unsigned*)kp;
                bf[nt][1] = *(const unsigned*)(kp + 8);
            }
            #pragma unroll
            for (int mt = 0; mt < 2; mt++)
                #pragma unroll
                for (int nt = 0; nt < 4; nt++)
                    MMA_F16(s[mt][nt], aq[mt][kt], bf[nt]);
        }
        #pragma unroll
        for (int nt = 0; nt < 4; nt++) {
            float2 bv = *reinterpret_cast<const float2*>(&bi[kb + nt*8 + 2*kk]);
            #pragma unroll
            for (int mt = 0; mt < 2; mt++) {
                s[mt][nt][0] = s[mt][nt][0]*SCL + bv.x;
                s[mt][nt][1] = s[mt][nt][1]*SCL + bv.y;
                s[mt][nt][2] = s[mt][nt][2]*SCL + bv.x;
                s[mt][nt][3] = s[mt][nt][3]*SCL + bv.y;
            }
        }
        #pragma unroll
        for (int mt = 0; mt < 2; mt++) {
            #pragma unroll
            for (int hf = 0; hf < 2; hf++) {
                float tm = -1e30f;
                #pragma unroll
                for (int nt = 0; nt < 4; nt++)
                    tm = fmaxf(tm, fmaxf(s[mt][nt][2*hf], s[mt][nt][2*hf+1]));
                tm = fmaxf(tm, __shfl_xor_sync(0xffffffffu, tm, 1));
                tm = fmaxf(tm, __shfl_xor_sync(0xffffffffu, tm, 2));
                float nm = fmaxf(m_[mt][hf], tm);
                float corr = __expf(m_[mt][hf] - nm);
                m_[mt][hf] = nm;
                float rs = 0.f;
                #pragma unroll
                for (int nt = 0; nt < 4; nt++) {
                    float p0 = __expf(s[mt][nt][2*hf] - nm);
                    float p1 = __expf(s[mt][nt][2*hf+1] - nm);
                    s[mt][nt][2*hf] = p0; s[mt][nt][2*hf+1] = p1;
                    rs += p0 + p1;
                    o[mt][nt][2*hf]   *= corr;
                    o[mt][nt][2*hf+1] *= corr;
                }
                rs += __shfl_xor_sync(0xffffffffu, rs, 1);
                rs += __shfl_xor_sync(0xffffffffu, rs, 2);
                l_[mt][hf] = l_[mt][hf]*corr + rs;
            }
        }
        #pragma unroll
        for (int mt = 0; mt < 2; mt++)
            #pragma unroll
            for (int nt = 0; nt < 4; nt++) {
                *reinterpret_cast<__half2*>(&pw[(mt*16+gr)*40 + nt*8 + 2*kk]) =
                    __floats2half2_rn(s[mt][nt][0], s[mt][nt][1]);
                *reinterpret_cast<__half2*>(&pw[(mt*16+gr+8)*40 + nt*8 + 2*kk]) =
                    __floats2half2_rn(s[mt][nt][2], s[mt][nt][3]);
            }
        __syncwarp();
        #pragma unroll
        for (int kt = 0; kt < 2; kt++) {
            unsigned ap[2][4];
            #pragma unroll
            for (int mt = 0; mt < 2; mt++) {
                const __half* pp = &pw[(mt*16+gr)*40 + kt*16 + 2*kk];
                ap[mt][0] = *(const unsigned*)pp;
                ap[mt][1] = *(const unsigned*)(pp + 8*40);
                ap[mt][2] = *(const unsigned*)(pp + 8);
                ap[mt][3] = *(const unsigned*)(pp + 8*40 + 8);
            }
            unsigned bf[4][2];
            #pragma unroll
            for (int nt = 0; nt < 4; nt++) {
                const __half* vp = &Vth[(nt*8+gr)*264 + kb + kt*16 + 2*kk];
                bf[nt][0] = *(const unsigned*)vp;
                bf[nt][1] = *(const unsigned*)(vp + 8);
            }
            #pragma unroll
            for (int mt = 0; mt < 2; mt++)
                #pragma unroll
                for (int nt = 0; nt < 4; nt++)
                    MMA_F16(o[mt][nt], ap[mt], bf[nt]);
        }
        __syncwarp();
    }

    #pragma unroll
    for (int mt = 0; mt < 2; mt++) {
        float i0 = 1.f / l_[mt][0], i1 = 1.f / l_[mt][1];
        #pragma unroll
        for (int nt = 0; nt < 4; nt++) {
            size_t base = (size_t)(qrow0 + mt*16)*Hsz + h*DHs + nt*8 + 2*kk;
            *reinterpret_cast<__half2*>(&ctx[base]) =
                __floats2half2_rn(o[mt][nt][0]*i0, o[mt][nt][1]*i0);
            *reinterpret_cast<__half2*>(&ctx[base + 8*(size_t)Hsz]) =
                __floats2half2_rn(o[mt][nt][2]*i1, o[mt][nt][3]*i1);
        }
    }
}

// ---------------- residual + LN (warp per row; all-half storage) ----------------
__global__ __launch_bounds__(256) void residual_ln_kernel(
        const __half* __restrict__ delta,
        const float* __restrict__ g, const float* __restrict__ b) {
    const int lane = threadIdx.x & 31, w = threadIdx.x >> 5;
    const int row = blockIdx.x * 8 + w;
    __half2* hp = reinterpret_cast<__half2*>(g_hh + (size_t)row * Hsz);
    const __half2* dp = reinterpret_cast<const __half2*>(delta + (size_t)row * Hsz);
    float4 x[3];
    float sum = 0.f;
    #pragma unroll
    for (int i = 0; i < 3; i++) {
        int j = lane + i * 32;
        float2 h0 = __half22float2(hp[2*j]);
        float2 h1 = __half22float2(hp[2*j + 1]);
        float2 d0 = __half22float2(dp[2*j]);
        float2 d1 = __half22float2(dp[2*j + 1]);
        x[i] = make_float4(h0.x + d0.x, h0.y + d0.y, h1.x + d1.x, h1.y + d1.y);
        sum += x[i].x + x[i].y + x[i].z + x[i].w;
    }
    #pragma unroll
    for (int o = 16; o > 0; o >>= 1) sum += __shfl_xor_sync(0xffffffffu, sum, o);
    float mean = sum * (1.f / Hsz);
    float sq = 0.f;
    #pragma unroll
    for (int i = 0; i < 3; i++) {
        float dx = x[i].x - mean, dy = x[i].y - mean, dz = x[i].z - mean, dw = x[i].w - mean;
        sq += dx*dx + dy*dy + dz*dz + dw*dw;
    }
    #pragma unroll
    for (int o = 16; o > 0; o >>= 1) sq += __shfl_xor_sync(0xffffffffu, sq, o);
    float inv = rsqrtf(sq * (1.f / Hsz) + 1e-12f);
    const float4* gp = reinterpret_cast<const float4*>(g);
    const float4* bp = reinterpret_cast<const float4*>(b);
    #pragma unroll
    for (int i = 0; i < 3; i++) {
        int j = lane + i * 32;
        float4 gv = gp[j], bv = bp[j];
        hp[2*j] = __floats2half2_rn(gv.x * (x[i].x - mean) * inv + bv.x,
                                    gv.y * (x[i].y - mean) * inv + bv.y);
        hp[2*j + 1] = __floats2half2_rn(gv.z * (x[i].z - mean) * inv + bv.z,
                                        gv.w * (x[i].w - mean) * inv + bv.w);
    }
}

// ---------------- offramp (warp per document) -----------------------------------
__global__ void offramp_kernel(const float* __restrict__ Wr, const float* __restrict__ br,
                               int layer) {
    const int lane = threadIdx.x & 31, w = threadIdx.x >> 5;
    const int b = blockIdx.x * 8 + w;                 // 16 blocks x 8 warps = 128
    const __half* hr = g_hh + (size_t)(b * Ssz) * Hsz;
    const float* wr = Wr + layer * Hsz;
    float acc = 0.f;
    #pragma unroll
    for (int i = 0; i < 12; i++) {
        int j = lane + i * 32;
        acc = fmaf(__half2float(hr[j]), wr[j], acc);
    }
    #pragma unroll
    for (int o = 16; o > 0; o >>= 1) acc += __shfl_xor_sync(0xffffffffu, acc, o);
    if (lane == 0) {
        float l = acc + br[layer];
        float lsp = (l > 0.f) ? -log1pf(expf(-l)) : (l - log1pf(expf(l)));
        float lsn = (l < 0.f) ? -log1pf(expf(l)) : (-l - log1pf(expf(-l)));
        float p = 1.f / (1.f + expf(-l));
        float ent = -(p * lsp + (1.f - p) * lsn);
        if (g_active[b] && ent < 0.1f) {
            g_scores[b] = l; g_exitl[b] = layer; g_active[b] = 0;
        }
    }
}

// ---------------- pooler (half h input) -----------------------------------------
__global__ void pooler_kernel(const float* __restrict__ Wp, const float* __restrict__ bp) {
    __shared__ float hr[Hsz];
    int b = blockIdx.x, tid = threadIdx.x;   // 384 threads
    hr[tid] = __half2float(g_hh[(size_t)(b * Ssz) * Hsz + tid]);
    __syncthreads();
    float acc = bp[tid];
    for (int kk = 0; kk < Hsz; kk++) acc = fmaf(hr[kk], Wp[kk * Hsz + tid], acc);
    g_pooled[b * Hsz + tid] = tanhf(acc);
}

// ---------------- final classifier + output -------------------------------------
__global__ void final_kernel(const float* __restrict__ Wc, const float* __restrict__ bc,
                             float* __restrict__ out, int out_size) {
    __shared__ int counts[8];
    int tid = threadIdx.x;  // 128
    if (tid < 8) counts[tid] = 0;
    __syncthreads();
    int b = tid;
    float acc = bc[0];
    for (int kk = 0; kk < Hsz; kk++) acc = fmaf(g_pooled[b * Hsz + kk], Wc[kk], acc);
    float sc; int el;
    if (g_active[b]) { sc = acc; el = NOFF; }
    else             { sc = g_scores[b]; el = g_exitl[b]; }
    atomicAdd(&counts[el], 1);
    __syncthreads();
    out[b] = sc;
    out[Bsz + b] = (float)el;
    if (tid < NOFF + 1) out[2 * Bsz + tid] = (float)counts[tid];
    for (int i = 2 * Bsz + NOFF + 1 + tid; i < out_size; i += 128) out[i] = 0.f;
}

// ---------------- launch --------------------------------------------------------
extern "C" void kernel_launch(void* const* d_in, const int* in_sizes, int n_in,
                              void* d_out, int out_size) {
    (void)in_sizes; (void)n_in;
    const int*   input_ids      = (const int*)d_in[0];
    const int*   attention_mask = (const int*)d_in[1];
    const int*   token_type_ids = (const int*)d_in[2];
    const float* word_emb = (const float*)d_in[3];
    const float* pos_emb  = (const float*)d_in[4];
    const float* type_emb = (const float*)d_in[5];
    const float* emb_ln_g = (const float*)d_in[6];
    const float* emb_ln_b = (const float*)d_in[7];
    const float* Wq = (const float*)d_in[8];  const float* bq = (const float*)d_in[9];
    const float* Wk = (const float*)d_in[10]; const float* bk = (const float*)d_in[11];
    const float* Wv = (const float*)d_in[12]; const float* bv = (const float*)d_in[13];
    const float* Wo = (const float*)d_in[14]; const float* bo = (const float*)d_in[15];
    const float* ln1_g = (const float*)d_in[16]; const float* ln1_b = (const float*)d_in[17];
    const float* Wi = (const float*)d_in[18]; const float* bi = (const float*)d_in[19];
    const float* Wfo = (const float*)d_in[20]; const float* bfo = (const float*)d_in[21];
    const float* ln2_g = (const float*)d_in[22]; const float* ln2_b = (const float*)d_in[23];
    const float* Wp = (const float*)d_in[24]; const float* bp = (const float*)d_in[25];
    const float* Wc = (const float*)d_in[26]; const float* bc = (const float*)d_in[27];
    const float* Wr = (const float*)d_in[28]; const float* br = (const float*)d_in[29];

    __half *hhp, *qh, *kh, *vh, *ctxh, *tmph, *ffh;
    __half *whq, *whk, *whv, *who, *whi, *whfo;
    cudaGetSymbolAddress((void**)&hhp, g_hh);
    cudaGetSymbolAddress((void**)&qh, g_qh);
    cudaGetSymbolAddress((void**)&kh, g_kh);
    cudaGetSymbolAddress((void**)&vh, g_vh);
    cudaGetSymbolAddress((void**)&ctxh, g_ctxh);
    cudaGetSymbolAddress((void**)&tmph, g_tmph);
    cudaGetSymbolAddress((void**)&ffh, g_ffh);
    cudaGetSymbolAddress((void**)&whq, g_whq);
    cudaGetSymbolAddress((void**)&whk, g_whk);
    cudaGetSymbolAddress((void**)&whv, g_whv);
    cudaGetSymbolAddress((void**)&who, g_who);
    cudaGetSymbolAddress((void**)&whi, g_whi);
    cudaGetSymbolAddress((void**)&whfo, g_whfo);

    cudaFuncSetAttribute(attn_mma_kernel,
                         cudaFuncAttributeMaxDynamicSharedMemorySize, ATTN_SMEM_BYTES);

    init_state_kernel<<<1, 128>>>();
    embed_ln_kernel<<<ROWS, 128>>>(input_ids, token_type_ids, word_emb, pos_emb, type_emb,
                                   emb_ln_g, emb_ln_b);

    dim3 tb(32, 8);
    transpose_h_kernel<<<dim3(Hsz/32, Hsz/32, Lyr), tb>>>(Wq,  whq,  Hsz, Hsz);
    transpose_h_kernel<<<dim3(Hsz/32, Hsz/32, Lyr), tb>>>(Wk,  whk,  Hsz, Hsz);
    transpose_h_kernel<<<dim3(Hsz/32, Hsz/32, Lyr), tb>>>(Wv,  whv,  Hsz, Hsz);
    transpose_h_kernel<<<dim3(Hsz/32, Hsz/32, Lyr), tb>>>(Wo,  who,  Hsz, Hsz);
    transpose_h_kernel<<<dim3(Fsz/32, Hsz/32, Lyr), tb>>>(Wi,  whi,  Hsz, Fsz);
    transpose_h_kernel<<<dim3(Hsz/32, Fsz/32, Lyr), tb>>>(Wfo, whfo, Fsz, Hsz);

    dim3 gHH(Hsz / 128, ROWS / 128);          // (3, 256)
    dim3 gQKV(Hsz / 128, ROWS / 128, 3);      // (3, 256, 3)
    dim3 gHF(Fsz / 128, ROWS / 128);          // (12, 256)

    for (int i = 0; i < Lyr; i++) {
        hgemm_qkv_kernel<<<gQKV, 128>>>(hhp,
                    whq + (size_t)i * Hsz * Hsz, whk + (size_t)i * Hsz * Hsz,
                    whv + (size_t)i * Hsz * Hsz,
                    bq + i * Hsz, bk + i * Hsz, bv + i * Hsz,
                    qh, kh, vh);
        attn_mma_kernel<<<dim3(NHs, Bsz), 256, ATTN_SMEM_BYTES>>>(qh, kh, vh,
                                                                  attention_mask, ctxh);
        hgemm_kernel<<<gHH, 128>>>(ctxh, who + (size_t)i * Hsz * Hsz,
                                   bo + i * Hsz, tmph, Hsz, Hsz, 0);
        residual_ln_kernel<<<ROWS / 8, 256>>>(tmph, ln1_g + i * Hsz, ln1_b + i * Hsz);
        hgemm_kernel<<<gHF, 128>>>(hhp, whi + (size_t)i * Hsz * Fsz,
                                   bi + i * Fsz, ffh, Fsz, Hsz, 1);
        hgemm_kernel<<<gHH, 128>>>(ffh, whfo + (size_t)i * Fsz * Hsz,
                                   bfo + i * Hsz, tmph, Hsz, Fsz, 0);
        residual_ln_kernel<<<ROWS / 8, 256>>>(tmph, ln2_g + i * Hsz, ln2_b + i * Hsz);
        if (i < NOFF) {
            offramp_kernel<<<16, 256>>>(Wr, br, i);
        }
    }
    pooler_kernel<<<Bsz, Hsz>>>(Wp, bp);
    final_kernel<<<1, 128>>>(Wc, bc, (float*)d_out, out_size);
}

// round 17
// speedup vs baseline: 1.1185x; 1.0071x over previous
#include <cuda_runtime.h>
#include <cuda_fp16.h>
#include <math.h>

#define Bsz 128
#define Ssz 256
#define Hsz 384
#define NHs 12
#define DHs 32
#define Fsz 1536
#define Lyr 6
#define NOFF 5
#define ROWS (Bsz*Ssz)   /* 32768 */

// ---------------- scratch (static device globals; no allocation) --------------
__device__ __half g_hh[ROWS*Hsz];        // residual stream h (half)
__device__ __half g_qh[ROWS*Hsz];
__device__ __half g_kh[ROWS*Hsz];
__device__ __half g_vh[ROWS*Hsz];
__device__ __half g_ctxh[ROWS*Hsz];      // attention output (half)
__device__ __half g_tmph[ROWS*Hsz];      // residual delta (half)
__device__ __half g_ffh[ROWS*Fsz];       // FFN intermediate (half)
__device__ float  g_pooled[Bsz*Hsz];
__device__ int    g_active[Bsz];
__device__ float  g_scores[Bsz];
__device__ int    g_exitl[Bsz];
// transposed half weights: Wt[n][k] = (half)W[k][n]
__device__ __half g_whq[Lyr*Hsz*Hsz];
__device__ __half g_whk[Lyr*Hsz*Hsz];
__device__ __half g_whv[Lyr*Hsz*Hsz];
__device__ __half g_who[Lyr*Hsz*Hsz];
__device__ __half g_whi[Lyr*Hsz*Fsz];
__device__ __half g_whfo[Lyr*Fsz*Hsz];

// ---------------- helpers ------------------------------------------------------
__device__ __forceinline__ float blockReduceSum128(float val, float* smem4) {
    int lane = threadIdx.x & 31, warp = threadIdx.x >> 5;
    #pragma unroll
    for (int o = 16; o > 0; o >>= 1) val += __shfl_down_sync(0xffffffffu, val, o);
    if (lane == 0) smem4[warp] = val;
    __syncthreads();
    float v = (threadIdx.x < 4) ? smem4[threadIdx.x] : 0.f;
    if (warp == 0) {
        v += __shfl_down_sync(0xffffffffu, v, 2);
        v += __shfl_down_sync(0xffffffffu, v, 1);
        if (lane == 0) smem4[0] = v;
    }
    __syncthreads();
    float r = smem4[0];
    __syncthreads();
    return r;
}

__device__ __forceinline__ void cpasync16(void* dst, const void* src) {
    unsigned sa = (unsigned)__cvta_generic_to_shared(dst);
    asm volatile("cp.async.cg.shared.global [%0], [%1], 16;\n" :: "r"(sa), "l"(src));
}
__device__ __forceinline__ void cp_commit() { asm volatile("cp.async.commit_group;\n"); }
__device__ __forceinline__ void cp_wait0()  { asm volatile("cp.async.wait_group 0;\n"); }

#define MMA_F16(d, a, bfr) \
    asm volatile("mma.sync.aligned.m16n8k16.row.col.f32.f16.f16.f32 " \
        "{%0,%1,%2,%3}, {%4,%5,%6,%7}, {%8,%9}, {%0,%1,%2,%3};" \
        : "+f"((d)[0]), "+f"((d)[1]), "+f"((d)[2]), "+f"((d)[3]) \
        : "r"((a)[0]), "r"((a)[1]), "r"((a)[2]), "r"((a)[3]), \
          "r"((bfr)[0]), "r"((bfr)[1]))

// ---------------- state init ---------------------------------------------------
__global__ void init_state_kernel() {
    int t = threadIdx.x;
    if (t < Bsz) { g_active[t] = 1; g_scores[t] = 0.f; g_exitl[t] = 0; }
}

// ---------------- weight transpose + fp16 convert: dst[n][k] = (half)src[k][n] -
__global__ void transpose_h_kernel(const float* __restrict__ src, __half* __restrict__ dst,
                                   int K, int N) {
    __shared__ float tile[32][33];
    const float* s = src + (size_t)blockIdx.z * K * N;
    __half* d = dst + (size_t)blockIdx.z * K * N;
    int n0 = blockIdx.x * 32, k0 = blockIdx.y * 32;
    #pragma unroll
    for (int i = threadIdx.y; i < 32; i += 8)
        tile[i][threadIdx.x] = s[(size_t)(k0 + i) * N + n0 + threadIdx.x];
    __syncthreads();
    #pragma unroll
    for (int i = threadIdx.y; i < 32; i += 8)
        d[(size_t)(n0 + i) * K + k0 + threadIdx.x] = __float2half_rn(tile[threadIdx.x][i]);
}

// ---------------- embeddings + LN (writes half h) ------------------------------
__global__ void embed_ln_kernel(const int* __restrict__ ids, const int* __restrict__ tts,
                                const float* __restrict__ we, const float* __restrict__ pe,
                                const float* __restrict__ te, const float* __restrict__ g,
                                const float* __restrict__ b) {
    __shared__ float red[4];
    int row = blockIdx.x, s = row & (Ssz - 1), tid = threadIdx.x;
    int id = ids[row], tt = tts[row];
    float x[3];
    #pragma unroll
    for (int i = 0; i < 3; i++) {
        int j = tid + i * 128;
        x[i] = we[id * Hsz + j] + pe[s * Hsz + j] + te[tt * Hsz + j];
    }
    float mean = blockReduceSum128(x[0] + x[1] + x[2], red) * (1.f / Hsz);
    float sq = 0.f;
    #pragma unroll
    for (int i = 0; i < 3; i++) { float d = x[i] - mean; sq += d * d; }
    float var = blockReduceSum128(sq, red) * (1.f / Hsz);
    float inv = rsqrtf(var + 1e-12f);
    #pragma unroll
    for (int i = 0; i < 3; i++) {
        int j = tid + i * 128;
        float o = g[j] * (x[i] - mean) * inv + b[j];
        g_hh[(size_t)row * Hsz + j] = __float2half_rn(o);
    }
}

// ---------------- FP16 tensor-core GEMM (128x128 block, 64x64 warp tile) -------
struct HgemmSmem {
    __half As[2][128][40];
    __half Bs[2][128][40];
};

__device__ __forceinline__ void hgemm_body(
        const __half* __restrict__ A, const __half* __restrict__ Wt,
        const float* __restrict__ bias, __half* __restrict__ Ch,
        int N, int K, int act, int bx, int by, HgemmSmem& sm) {
    const int t = threadIdx.x;     // 128
    const int lane = t & 31, warp = t >> 5;
    const int kk = lane & 3, gr = lane >> 2;
    const int mw = (warp >> 1) * 64;
    const int nw = (warp & 1) * 64;
    const int br = by * 128, bc = bx * 128;

    const int rbase = t >> 2, cc = t & 3;
    const __half* Ag = A + (size_t)(br + rbase) * K + cc * 8;
    const __half* Bg = Wt + (size_t)(bc + rbase) * K + cc * 8;

    float acc[4][8][4] = {};
    const int T = K >> 5;

    #define HGL(k0, buf) do { \
        _Pragma("unroll") \
        for (int i_ = 0; i_ < 4; i_++) { \
            cpasync16(&sm.As[buf][rbase + 32*i_][cc*8], Ag + (size_t)(32*i_) * K + (k0)); \
            cpasync16(&sm.Bs[buf][rbase + 32*i_][cc*8], Bg + (size_t)(32*i_) * K + (k0)); \
        } \
        cp_commit(); \
    } while (0)

    HGL(0, 0);
    int buf = 0;
    for (int tt = 0; tt < T; tt++) {
        cp_wait0();
        __syncthreads();
        if (tt + 1 < T) HGL((tt + 1) << 5, buf ^ 1);
        #pragma unroll
        for (int ks = 0; ks < 32; ks += 16) {
            unsigned a[4][4], b[8][2];
            #pragma unroll
            for (int mt = 0; mt < 4; mt++) {
                int m = mw + mt * 16 + gr;
                a[mt][0] = *(const unsigned*)&sm.As[buf][m][ks + 2*kk];
                a[mt][1] = *(const unsigned*)&sm.As[buf][m + 8][ks + 2*kk];
                a[mt][2] = *(const unsigned*)&sm.As[buf][m][ks + 2*kk + 8];
                a[mt][3] = *(const unsigned*)&sm.As[buf][m + 8][ks + 2*kk + 8];
            }
            #pragma unroll
            for (int nt = 0; nt < 8; nt++) {
                int n = nw + nt * 8 + gr;
                b[nt][0] = *(const unsigned*)&sm.Bs[buf][n][ks + 2*kk];
                b[nt][1] = *(const unsigned*)&sm.Bs[buf][n][ks + 2*kk + 8];
            }
            #pragma unroll
            for (int mt = 0; mt < 4; mt++)
                #pragma unroll
                for (int nt = 0; nt < 8; nt++)
                    MMA_F16(acc[mt][nt], a[mt], b[nt]);
        }
        __syncthreads();
        buf ^= 1;
    }
    #undef HGL

    #pragma unroll
    for (int nt = 0; nt < 8; nt++) {
        int col = bc + nw + nt * 8 + 2 * kk;
        float b0 = bias[col], b1 = bias[col + 1];
        #pragma unroll
        for (int mt = 0; mt < 4; mt++) {
            int row = br + mw + mt * 16 + gr;
            float v0 = acc[mt][nt][0] + b0, v1 = acc[mt][nt][1] + b1;
            float v2 = acc[mt][nt][2] + b0, v3 = acc[mt][nt][3] + b1;
            if (act == 1) {
                v0 = 0.5f * v0 * (1.f + erff(v0 * 0.70710678118654752f));
                v1 = 0.5f * v1 * (1.f + erff(v1 * 0.70710678118654752f));
                v2 = 0.5f * v2 * (1.f + erff(v2 * 0.70710678118654752f));
                v3 = 0.5f * v3 * (1.f + erff(v3 * 0.70710678118654752f));
            }
            *reinterpret_cast<__half2*>(&Ch[(size_t)row * N + col]) =
                __floats2half2_rn(v0, v1);
            *reinterpret_cast<__half2*>(&Ch[(size_t)(row + 8) * N + col]) =
                __floats2half2_rn(v2, v3);
        }
    }
}

__global__ __launch_bounds__(128, 2) void hgemm_kernel(
        const __half* __restrict__ A, const __half* __restrict__ Wt,
        const float* __restrict__ bias, __half* __restrict__ Ch,
        int N, int K, int act) {
    __shared__ HgemmSmem sm;
    hgemm_body(A, Wt, bias, Ch, N, K, act, blockIdx.x, blockIdx.y, sm);
}

__global__ __launch_bounds__(128, 2) void hgemm_qkv_kernel(
        const __half* __restrict__ A,
        const __half* __restrict__ Wtq, const __half* __restrict__ Wtk, const __half* __restrict__ Wtv,
        const float* __restrict__ bq, const float* __restrict__ bk, const float* __restrict__ bv,
        __half* __restrict__ Cq, __half* __restrict__ Ck, __half* __restrict__ Cv) {
    __shared__ HgemmSmem sm;
    const __half* Ws[3] = {Wtq, Wtk, Wtv};
    const float* bs[3] = {bq, bk, bv};
    __half* Cs[3] = {Cq, Ck, Cv};
    int z = blockIdx.z;
    hgemm_body(A, Ws[z], bs[z], Cs[z], Hsz, Hsz, 0, blockIdx.x, blockIdx.y, sm);
}

// ---------------- fp16 tensor-core flash attention (vectorized staging) --------
#define ATTN_SMEM_BYTES (256*40*2 + 32*264*2 + 8*32*40*2 + 256*4)
#define SCL 0.17677669529663688f

__global__ __launch_bounds__(256, 2) void attn_mma_kernel(
        const __half* __restrict__ q, const __half* __restrict__ k,
        const __half* __restrict__ v, const int* __restrict__ mask,
        __half* __restrict__ ctx) {
    extern __shared__ char smraw[];
    __half* Ksh = reinterpret_cast<__half*>(smraw);              // [256][40]
    __half* Vth = Ksh + 256*40;                                  // [32][264]
    __half* Pwh = Vth + 32*264;                                  // [8][32][40]
    float*  bi  = reinterpret_cast<float*>(Pwh + 8*32*40);       // [256]

    const int h = blockIdx.x, b = blockIdx.y;
    const int tid = threadIdx.x, lane = tid & 31, w = tid >> 5;
    const int gr = lane >> 2, kk = lane & 3;

    // vectorized staging: 1024 (key, 8-half-chunk) tasks, uint4 global loads
    #pragma unroll
    for (int i = 0; i < 4; i++) {
        int task = tid + i * 256;
        int key = task >> 2, c = task & 3;
        size_t gbase = (size_t)(b*Ssz + key)*Hsz + h*DHs + c*8;
        // K: direct aligned 16B copy into row-major smem
        *reinterpret_cast<uint4*>(&Ksh[key*40 + c*8]) =
            *reinterpret_cast<const uint4*>(k + gbase);
        // V: 16B load, scatter-transpose into Vth[d][key]
        uint4 vv = *reinterpret_cast<const uint4*>(v + gbase);
        const __half2* v2 = reinterpret_cast<const __half2*>(&vv);
        #pragma unroll
        for (int e = 0; e < 4; e++) {
            __half2 p = v2[e];
            Vth[(c*8 + 2*e) * 264 + key] = __low2half(p);
            Vth[(c*8 + 2*e + 1) * 264 + key] = __high2half(p);
        }
    }
    bi[tid] = (1.f - (float)mask[b*Ssz + tid]) * -1e9f;
    __syncthreads();

    unsigned aq[2][2][4];
    const int qrow0 = b*Ssz + w*32 + gr;
    #pragma unroll
    for (int mt = 0; mt < 2; mt++)
        #pragma unroll
        for (int kt = 0; kt < 2; kt++) {
            const __half* qp = q + (size_t)(qrow0 + mt*16)*Hsz + h*DHs + kt*16 + 2*kk;
            aq[mt][kt][0] = *(const unsigned*)qp;
            aq[mt][kt][1] = *(const unsigned*)(qp + 8*(size_t)Hsz);
            aq[mt][kt][2] = *(const unsigned*)(qp + 8);
            aq[mt][kt][3] = *(const unsigned*)(qp + 8*(size_t)Hsz + 8);
        }

    float m_[2][2] = {{-1e30f, -1e30f}, {-1e30f, -1e30f}};
    float l_[2][2] = {};
    float o[2][4][4] = {};
    __half* pw = Pwh + w*(32*40);

    for (int t = 0; t < 8; t++) {
        const int kb = t*32;
        float s[2][4][4] = {};
        #pragma unroll
        for (int kt = 0; kt < 2; kt++) {
            unsigned bf[4][2];
            #pragma unroll
            for (int nt = 0; nt < 4; nt++) {
                const __half* kp = &Ksh[(kb + nt*8 + gr)*40 + kt*16 + 2*kk];
                bf[nt][0] = *(const unsigned*)kp;
                bf[nt][1] = *(const unsigned*)(kp + 8);
            }
            #pragma unroll
            for (int mt = 0; mt < 2; mt++)
                #pragma unroll
                for (int nt = 0; nt < 4; nt++)
                    MMA_F16(s[mt][nt], aq[mt][kt], bf[nt]);
        }
        #pragma unroll
        for (int nt = 0; nt < 4; nt++) {
            float2 bv = *reinterpret_cast<const float2*>(&bi[kb + nt*8 + 2*kk]);
            #pragma unroll
            for (int mt = 0; mt < 2; mt++) {
                s[mt][nt][0] = s[mt][nt][0]*SCL + bv.x;
                s[mt][nt][1] = s[mt][nt][1]*SCL + bv.y;
                s[mt][nt][2] = s[mt][nt][2]*SCL + bv.x;
                s[mt][nt][3] = s[mt][nt][3]*SCL + bv.y;
            }
        }
        #pragma unroll
        for (int mt = 0; mt < 2; mt++) {
            #pragma unroll
            for (int hf = 0; hf < 2; hf++) {
                float tm = -1e30f;
                #pragma unroll
                for (int nt = 0; nt < 4; nt++)
                    tm = fmaxf(tm, fmaxf(s[mt][nt][2*hf], s[mt][nt][2*hf+1]));
                tm = fmaxf(tm, __shfl_xor_sync(0xffffffffu, tm, 1));
                tm = fmaxf(tm, __shfl_xor_sync(0xffffffffu, tm, 2));
                float nm = fmaxf(m_[mt][hf], tm);
                float corr = __expf(m_[mt][hf] - nm);
                m_[mt][hf] = nm;
                float rs = 0.f;
                #pragma unroll
                for (int nt = 0; nt < 4; nt++) {
                    float p0 = __expf(s[mt][nt][2*hf] - nm);
                    float p1 = __expf(s[mt][nt][2*hf+1] - nm);
                    s[mt][nt][2*hf] = p0; s[mt][nt][2*hf+1] = p1;
                    rs += p0 + p1;
                    o[mt][nt][2*hf]   *= corr;
                    o[mt][nt][2*hf+1] *= corr;
                }
                rs += __shfl_xor_sync(0xffffffffu, rs, 1);
                rs += __shfl_xor_sync(0xffffffffu, rs, 2);
                l_[mt][hf] = l_[mt][hf]*corr + rs;
            }
        }
        #pragma unroll
        for (int mt = 0; mt < 2; mt++)
            #pragma unroll
            for (int nt = 0; nt < 4; nt++) {
                *reinterpret_cast<__half2*>(&pw[(mt*16+gr)*40 + nt*8 + 2*kk]) =
                    __floats2half2_rn(s[mt][nt][0], s[mt][nt][1]);
                *reinterpret_cast<__half2*>(&pw[(mt*16+gr+8)*40 + nt*8 + 2*kk]) =
                    __floats2half2_rn(s[mt][nt][2], s[mt][nt][3]);
            }
        __syncwarp();
        #pragma unroll
        for (int kt = 0; kt < 2; kt++) {
            unsigned ap[2][4];
            #pragma unroll
            for (int mt = 0; mt < 2; mt++) {
                const __half* pp = &pw[(mt*16+gr)*40 + kt*16 + 2*kk];
                ap[mt][0] = *(const unsigned*)pp;
                ap[mt][1] = *(const unsigned*)(pp + 8*40);
                ap[mt][2] = *(const unsigned*)(pp + 8);
                ap[mt][3] = *(const unsigned*)(pp + 8*40 + 8);
            }
            unsigned bf[4][2];
            #pragma unroll
            for (int nt = 0; nt < 4; nt++) {
                const __half* vp = &Vth[(nt*8+gr)*264 + kb + kt*16 + 2*kk];
                bf[nt][0] = *(const unsigned*)vp;
                bf[nt][1] = *(const unsigned*)(vp + 8);
            }
            #pragma unroll
            for (int mt = 0; mt < 2; mt++)
                #pragma unroll
                for (int nt = 0; nt < 4; nt++)
                    MMA_F16(o[mt][nt], ap[mt], bf[nt]);
        }
        __syncwarp();
    }

    #pragma unroll
    for (int mt = 0; mt < 2; mt++) {
        float i0 = 1.f / l_[mt][0], i1 = 1.f / l_[mt][1];
        #pragma unroll
        for (int nt = 0; nt < 4; nt++) {
            size_t base = (size_t)(qrow0 + mt*16)*Hsz + h*DHs + nt*8 + 2*kk;
            *reinterpret_cast<__half2*>(&ctx[base]) =
                __floats2half2_rn(o[mt][nt][0]*i0, o[mt][nt][1]*i0);
            *reinterpret_cast<__half2*>(&ctx[base + 8*(size_t)Hsz]) =
                __floats2half2_rn(o[mt][nt][2]*i1, o[mt][nt][3]*i1);
        }
    }
}

// ---------------- residual + LN (warp per row; all-half storage) ----------------
__global__ __launch_bounds__(256) void residual_ln_kernel(
        const __half* __restrict__ delta,
        const float* __restrict__ g, const float* __restrict__ b) {
    const int lane = threadIdx.x & 31, w = threadIdx.x >> 5;
    const int row = blockIdx.x * 8 + w;
    __half2* hp = reinterpret_cast<__half2*>(g_hh + (size_t)row * Hsz);
    const __half2* dp = reinterpret_cast<const __half2*>(delta + (size_t)row * Hsz);
    float4 x[3];
    float sum = 0.f;
    #pragma unroll
    for (int i = 0; i < 3; i++) {
        int j = lane + i * 32;
        float2 h0 = __half22float2(hp[2*j]);
        float2 h1 = __half22float2(hp[2*j + 1]);
        float2 d0 = __half22float2(dp[2*j]);
        float2 d1 = __half22float2(dp[2*j + 1]);
        x[i] = make_float4(h0.x + d0.x, h0.y + d0.y, h1.x + d1.x, h1.y + d1.y);
        sum += x[i].x + x[i].y + x[i].z + x[i].w;
    }
    #pragma unroll
    for (int o = 16; o > 0; o >>= 1) sum += __shfl_xor_sync(0xffffffffu, sum, o);
    float mean = sum * (1.f / Hsz);
    float sq = 0.f;
    #pragma unroll
    for (int i = 0; i < 3; i++) {
        float dx = x[i].x - mean, dy = x[i].y - mean, dz = x[i].z - mean, dw = x[i].w - mean;
        sq += dx*dx + dy*dy + dz*dz + dw*dw;
    }
    #pragma unroll
    for (int o = 16; o > 0; o >>= 1) sq += __shfl_xor_sync(0xffffffffu, sq, o);
    float inv = rsqrtf(sq * (1.f / Hsz) + 1e-12f);
    const float4* gp = reinterpret_cast<const float4*>(g);
    const float4* bp = reinterpret_cast<const float4*>(b);
    #pragma unroll
    for (int i = 0; i < 3; i++) {
        int j = lane + i * 32;
        float4 gv = gp[j], bv = bp[j];
        hp[2*j] = __floats2half2_rn(gv.x * (x[i].x - mean) * inv + bv.x,
                                    gv.y * (x[i].y - mean) * inv + bv.y);
        hp[2*j + 1] = __floats2half2_rn(gv.z * (x[i].z - mean) * inv + bv.z,
                                        gv.w * (x[i].w - mean) * inv + bv.w);
    }
}

// ---------------- offramp (warp per document) -----------------------------------
__global__ void offramp_kernel(const float* __restrict__ Wr, const float* __restrict__ br,
                               int layer) {
    const int lane = threadIdx.x & 31, w = threadIdx.x >> 5;
    const int b = blockIdx.x * 8 + w;                 // 16 blocks x 8 warps = 128
    const __half* hr = g_hh + (size_t)(b * Ssz) * Hsz;
    const float* wr = Wr + layer * Hsz;
    float acc = 0.f;
    #pragma unroll
    for (int i = 0; i < 12; i++) {
        int j = lane + i * 32;
        acc = fmaf(__half2float(hr[j]), wr[j], acc);
    }
    #pragma unroll
    for (int o = 16; o > 0; o >>= 1) acc += __shfl_xor_sync(0xffffffffu, acc, o);
    if (lane == 0) {
        float l = acc + br[layer];
        float lsp = (l > 0.f) ? -log1pf(expf(-l)) : (l - log1pf(expf(l)));
        float lsn = (l < 0.f) ? -log1pf(expf(l)) : (-l - log1pf(expf(-l)));
        float p = 1.f / (1.f + expf(-l));
        float ent = -(p * lsp + (1.f - p) * lsn);
        if (g_active[b] && ent < 0.1f) {
            g_scores[b] = l; g_exitl[b] = layer; g_active[b] = 0;
        }
    }
}

// ---------------- pooler (half h input) -----------------------------------------
__global__ void pooler_kernel(const float* __restrict__ Wp, const float* __restrict__ bp) {
    __shared__ float hr[Hsz];
    int b = blockIdx.x, tid = threadIdx.x;   // 384 threads
    hr[tid] = __half2float(g_hh[(size_t)(b * Ssz) * Hsz + tid]);
    __syncthreads();
    float acc = bp[tid];
    for (int kk = 0; kk < Hsz; kk++) acc = fmaf(hr[kk], Wp[kk * Hsz + tid], acc);
    g_pooled[b * Hsz + tid] = tanhf(acc);
}

// ---------------- final classifier + output -------------------------------------
__global__ void final_kernel(const float* __restrict__ Wc, const float* __restrict__ bc,
                             float* __restrict__ out, int out_size) {
    __shared__ int counts[8];
    int tid = threadIdx.x;  // 128
    if (tid < 8) counts[tid] = 0;
    __syncthreads();
    int b = tid;
    float acc = bc[0];
    for (int kk = 0; kk < Hsz; kk++) acc = fmaf(g_pooled[b * Hsz + kk], Wc[kk], acc);
    float sc; int el;
    if (g_active[b]) { sc = acc; el = NOFF; }
    else             { sc = g_scores[b]; el = g_exitl[b]; }
    atomicAdd(&counts[el], 1);
    __syncthreads();
    out[b] = sc;
    out[Bsz + b] = (float)el;
    if (tid < NOFF + 1) out[2 * Bsz + tid] = (float)counts[tid];
    for (int i = 2 * Bsz + NOFF + 1 + tid; i < out_size; i += 128) out[i] = 0.f;
}

// ---------------- launch --------------------------------------------------------
extern "C" void kernel_launch(void* const* d_in, const int* in_sizes, int n_in,
                              void* d_out, int out_size) {
    (void)in_sizes; (void)n_in;
    const int*   input_ids      = (const int*)d_in[0];
    const int*   attention_mask = (const int*)d_in[1];
    const int*   token_type_ids = (const int*)d_in[2];
    const float* word_emb = (const float*)d_in[3];
    const float* pos_emb  = (const float*)d_in[4];
    const float* type_emb = (const float*)d_in[5];
    const float* emb_ln_g = (const float*)d_in[6];
    const float* emb_ln_b = (const float*)d_in[7];
    const float* Wq = (const float*)d_in[8];  const float* bq = (const float*)d_in[9];
    const float* Wk = (const float*)d_in[10]; const float* bk = (const float*)d_in[11];
    const float* Wv = (const float*)d_in[12]; const float* bv = (const float*)d_in[13];
    const float* Wo = (const float*)d_in[14]; const float* bo = (const float*)d_in[15];
    const float* ln1_g = (const float*)d_in[16]; const float* ln1_b = (const float*)d_in[17];
    const float* Wi = (const float*)d_in[18]; const float* bi = (const float*)d_in[19];
    const float* Wfo = (const float*)d_in[20]; const float* bfo = (const float*)d_in[21];
    const float* ln2_g = (const float*)d_in[22]; const float* ln2_b = (const float*)d_in[23];
    const float* Wp = (const float*)d_in[24]; const float* bp = (const float*)d_in[25];
    const float* Wc = (const float*)d_in[26]; const float* bc = (const float*)d_in[27];
    const float* Wr = (const float*)d_in[28]; const float* br = (const float*)d_in[29];

    __half *hhp, *qh, *kh, *vh, *ctxh, *tmph, *ffh;
    __half *whq, *whk, *whv, *who, *whi, *whfo;
    cudaGetSymbolAddress((void**)&hhp, g_hh);
    cudaGetSymbolAddress((void**)&qh, g_qh);
    cudaGetSymbolAddress((void**)&kh, g_kh);
    cudaGetSymbolAddress((void**)&vh, g_vh);
    cudaGetSymbolAddress((void**)&ctxh, g_ctxh);
    cudaGetSymbolAddress((void**)&tmph, g_tmph);
    cudaGetSymbolAddress((void**)&ffh, g_ffh);
    cudaGetSymbolAddress((void**)&whq, g_whq);
    cudaGetSymbolAddress((void**)&whk, g_whk);
    cudaGetSymbolAddress((void**)&whv, g_whv);
    cudaGetSymbolAddress((void**)&who, g_who);
    cudaGetSymbolAddress((void**)&whi, g_whi);
    cudaGetSymbolAddress((void**)&whfo, g_whfo);

    cudaFuncSetAttribute(attn_mma_kernel,
                         cudaFuncAttributeMaxDynamicSharedMemorySize, ATTN_SMEM_BYTES);

    init_state_kernel<<<1, 128>>>();
    embed_ln_kernel<<<ROWS, 128>>>(input_ids, token_type_ids, word_emb, pos_emb, type_emb,
                                   emb_ln_g, emb_ln_b);

    dim3 tb(32, 8);
    transpose_h_kernel<<<dim3(Hsz/32, Hsz/32, Lyr), tb>>>(Wq,  whq,  Hsz, Hsz);
    transpose_h_kernel<<<dim3(Hsz/32, Hsz/32, Lyr), tb>>>(Wk,  whk,  Hsz, Hsz);
    transpose_h_kernel<<<dim3(Hsz/32, Hsz/32, Lyr), tb>>>(Wv,  whv,  Hsz, Hsz);
    transpose_h_kernel<<<dim3(Hsz/32, Hsz/32, Lyr), tb>>>(Wo,  who,  Hsz, Hsz);
    transpose_h_kernel<<<dim3(Fsz/32, Hsz/32, Lyr), tb>>>(Wi,  whi,  Hsz, Fsz);
    transpose_h_kernel<<<dim3(Hsz/32, Fsz/32, Lyr), tb>>>(Wfo, whfo, Fsz, Hsz);

    dim3 gHH(Hsz / 128, ROWS / 128);          // (3, 256)
    dim3 gQKV(Hsz / 128, ROWS / 128, 3);      // (3, 256, 3)
    dim3 gHF(Fsz / 128, ROWS / 128);          // (12, 256)

    for (int i = 0; i < Lyr; i++) {
        hgemm_qkv_kernel<<<gQKV, 128>>>(hhp,
                    whq + (size_t)i * Hsz * Hsz, whk + (size_t)i * Hsz * Hsz,
                    whv + (size_t)i * Hsz * Hsz,
                    bq + i * Hsz, bk + i * Hsz, bv + i * Hsz,
                    qh, kh, vh);
        attn_mma_kernel<<<dim3(NHs, Bsz), 256, ATTN_SMEM_BYTES>>>(qh, kh, vh,
                                                                  attention_mask, ctxh);
        hgemm_kernel<<<gHH, 128>>>(ctxh, who + (size_t)i * Hsz * Hsz,
                                   bo + i * Hsz, tmph, Hsz, Hsz, 0);
        residual_ln_kernel<<<ROWS / 8, 256>>>(tmph, ln1_g + i * Hsz, ln1_b + i * Hsz);
        hgemm_kernel<<<gHF, 128>>>(hhp, whi + (size_t)i * Hsz * Fsz,
                                   bi + i * Fsz, ffh, Fsz, Hsz, 1);
        hgemm_kernel<<<gHH, 128>>>(ffh, whfo + (size_t)i * Fsz * Hsz,
                                   bfo + i * Hsz, tmph, Hsz, Fsz, 0);
        residual_ln_kernel<<<ROWS / 8, 256>>>(tmph, ln2_g + i * Hsz, ln2_b + i * Hsz);
        if (i < NOFF) {
            offramp_kernel<<<16, 256>>>(Wr, br, i);
        }
    }
    pooler_kernel<<<Bsz, Hsz>>>(Wp, bp);
    final_kernel<<<1, 128>>>(Wc, bc, (float*)d_out, out_size);
}